// round 14
// baseline (speedup 1.0000x reference)
#include <cuda_runtime.h>
#include <cuda_bf16.h>
#include <cstdint>
#include <math.h>

#define B_ 2
#define N_ 2048
#define D_ 768
#define H_ 12
#define HD_ 64
#define QKVSTRIDE (3 * D_)   // 2304
#define BH_ (B_ * H_)        // 24

// ---------------- scratch (allocation-free) ----------------
__device__ __nv_bfloat16 g_xh[(size_t)B_ * N_ * D_];
__device__ __nv_bfloat16 g_xl[(size_t)B_ * N_ * D_];
__device__ __nv_bfloat16 g_wqh[(size_t)QKVSTRIDE * D_];
__device__ __nv_bfloat16 g_wql[(size_t)QKVSTRIDE * D_];
__device__ __nv_bfloat16 g_aoh[(size_t)B_ * N_ * D_];
__device__ __nv_bfloat16 g_aol[(size_t)B_ * N_ * D_];
__device__ __nv_bfloat16 g_wph[(size_t)D_ * D_];
__device__ __nv_bfloat16 g_wpl[(size_t)D_ * D_];
__device__ __nv_bfloat16 g_qh[(size_t)BH_ * N_ * HD_];
__device__ __nv_bfloat16 g_ql[(size_t)BH_ * N_ * HD_];
__device__ __nv_bfloat16 g_kh[(size_t)BH_ * N_ * HD_];
__device__ __nv_bfloat16 g_kl[(size_t)BH_ * N_ * HD_];
__device__ __nv_bfloat16 g_vh[(size_t)BH_ * HD_ * N_];  // [bh][d][n]
__device__ __nv_bfloat16 g_vl[(size_t)BH_ * HD_ * N_];
__device__ float g_cosT[(size_t)N_ * HD_];
__device__ float g_sinT[(size_t)N_ * HD_];

// ---------------- helpers ----------------
__device__ __forceinline__ void ldsm_x4(uint32_t* r, const void* p) {
    uint32_t a = (uint32_t)__cvta_generic_to_shared(p);
    asm volatile("ldmatrix.sync.aligned.m8n8.x4.shared.b16 {%0,%1,%2,%3}, [%4];"
                 : "=r"(r[0]), "=r"(r[1]), "=r"(r[2]), "=r"(r[3]) : "r"(a));
}
__device__ __forceinline__ void ldsm_x2(uint32_t* r, const void* p) {
    uint32_t a = (uint32_t)__cvta_generic_to_shared(p);
    asm volatile("ldmatrix.sync.aligned.m8n8.x2.shared.b16 {%0,%1}, [%2];"
                 : "=r"(r[0]), "=r"(r[1]) : "r"(a));
}
__device__ __forceinline__ void mma16816(float* c, const uint32_t* a, const uint32_t* b) {
    asm volatile(
        "mma.sync.aligned.m16n8k16.row.col.f32.bf16.bf16.f32 "
        "{%0,%1,%2,%3}, {%4,%5,%6,%7}, {%8,%9}, {%0,%1,%2,%3};"
        : "+f"(c[0]), "+f"(c[1]), "+f"(c[2]), "+f"(c[3])
        : "r"(a[0]), "r"(a[1]), "r"(a[2]), "r"(a[3]), "r"(b[0]), "r"(b[1]));
}
// B operands passed as scalars (direct use of x4 results, no repack)
__device__ __forceinline__ void mma16816s(float* c, const uint32_t* a,
                                          uint32_t b0, uint32_t b1) {
    asm volatile(
        "mma.sync.aligned.m16n8k16.row.col.f32.bf16.bf16.f32 "
        "{%0,%1,%2,%3}, {%4,%5,%6,%7}, {%8,%9}, {%0,%1,%2,%3};"
        : "+f"(c[0]), "+f"(c[1]), "+f"(c[2]), "+f"(c[3])
        : "r"(a[0]), "r"(a[1]), "r"(a[2]), "r"(a[3]), "r"(b0), "r"(b1));
}
__device__ __forceinline__ void split2(float a, float b, uint32_t& h, uint32_t& l) {
    __nv_bfloat16 ha = __float2bfloat16(a), hb = __float2bfloat16(b);
    __nv_bfloat16 la = __float2bfloat16(a - __bfloat162float(ha));
    __nv_bfloat16 lb = __float2bfloat16(b - __bfloat162float(hb));
    h = (uint32_t)*(uint16_t*)&ha | ((uint32_t)*(uint16_t*)&hb << 16);
    l = (uint32_t)*(uint16_t*)&la | ((uint32_t)*(uint16_t*)&lb << 16);
}
__device__ __forceinline__ void cp16(void* s, const void* g) {
    uint32_t sa = (uint32_t)__cvta_generic_to_shared(s);
    asm volatile("cp.async.ca.shared.global [%0], [%1], 16;" :: "r"(sa), "l"(g));
}
#define CP_COMMIT() asm volatile("cp.async.commit_group;" ::: "memory")
#define CP_WAIT(n)  asm volatile("cp.async.wait_group %0;" :: "n"(n) : "memory")

// ---------------------------------------------------------------------------
// fused prologue: x split | Wqkv split | Wproj split | sincos table
// ---------------------------------------------------------------------------
#define NX4 ((B_ * N_ * D_) / 4)          // 786432
#define NW4 ((QKVSTRIDE * D_) / 4)        // 442368
#define NP4 ((D_ * D_) / 4)               // 147456
#define NS_ (N_ * HD_)                    // 131072
#define PRO_TOTAL (NX4 + NW4 + NP4 + NS_)

__global__ void prologue_kernel(const float4* __restrict__ x,
                                const float4* __restrict__ wq,
                                const float4* __restrict__ wp,
                                const float* __restrict__ pe)
{
    int i = blockIdx.x * blockDim.x + threadIdx.x;
    if (i < NX4) {
        float4 v = x[i];
        uint2 ho, lo;
        split2(v.x, v.y, ho.x, lo.x);
        split2(v.z, v.w, ho.y, lo.y);
        ((uint2*)g_xh)[i] = ho; ((uint2*)g_xl)[i] = lo;
    } else if (i < NX4 + NW4) {
        int j = i - NX4;
        float4 v = wq[j];
        uint2 ho, lo;
        split2(v.x, v.y, ho.x, lo.x);
        split2(v.z, v.w, ho.y, lo.y);
        ((uint2*)g_wqh)[j] = ho; ((uint2*)g_wql)[j] = lo;
    } else if (i < NX4 + NW4 + NP4) {
        int j = i - NX4 - NW4;
        float4 v = wp[j];
        uint2 ho, lo;
        split2(v.x, v.y, ho.x, lo.x);
        split2(v.z, v.w, ho.y, lo.y);
        ((uint2*)g_wph)[j] = ho; ((uint2*)g_wpl)[j] = lo;
    } else if (i < PRO_TOTAL) {
        int j = i - NX4 - NW4 - NP4;
        float s, c;
        sincosf(pe[j], &s, &c);
        g_sinT[j] = s;
        g_cosT[j] = c;
    }
}

// ---------------------------------------------------------------------------
// HMMA GEMM — R10 proven mainloop. EPI=0: plain+bias. EPI=1: fused RoPE +
// hi/lo split + V-transpose epilogue (QKV projection).
// ---------------------------------------------------------------------------
#define SSTR 40
#define GEMM_ASZ (128 * SSTR)
#define GEMM_STG (4 * GEMM_ASZ)
#define GEMM_SMEM (2 * GEMM_STG * 2)   // 81920 bytes
#define ESTR 132

template <int EPI>
__global__ __launch_bounds__(256) void gemm_mma_kernel(
    const __nv_bfloat16* __restrict__ Ah, const __nv_bfloat16* __restrict__ Al,
    const __nv_bfloat16* __restrict__ Wh, const __nv_bfloat16* __restrict__ Wl,
    const float* __restrict__ bias, float* __restrict__ C,
    int M, int Nc, int K)
{
    extern __shared__ __nv_bfloat16 gsm[];

    const int tid  = threadIdx.x;
    const int lane = tid & 31;
    const int wid  = tid >> 5;
    const int wm   = wid & 1;
    const int wn   = wid >> 1;
    const int m0   = blockIdx.y * 128;
    const int n0   = blockIdx.x * 128;

    float acc[4][4][4];
#pragma unroll
    for (int mt = 0; mt < 4; mt++)
#pragma unroll
        for (int nt = 0; nt < 4; nt++)
#pragma unroll
            for (int e = 0; e < 4; e++) acc[mt][nt][e] = 0.f;

    const int nkt = K / 32;

    auto load_stage = [&](int st, int t) {
        __nv_bfloat16* base = gsm + st * GEMM_STG;
        const int kk = t * 32;
        for (int f = tid; f < 512; f += 256) {
            int row = f >> 2;
            int ch  = (f & 3) * 8;
            size_t ga = (size_t)(m0 + row) * K + kk + ch;
            size_t gw = (size_t)(n0 + row) * K + kk + ch;
            int so = row * SSTR + ch;
            cp16(base + so,                Ah + ga);
            cp16(base + GEMM_ASZ + so,     Al + ga);
            cp16(base + 2 * GEMM_ASZ + so, Wh + gw);
            cp16(base + 3 * GEMM_ASZ + so, Wl + gw);
        }
    };

    load_stage(0, 0);
    CP_COMMIT();

    for (int t = 0; t < nkt; t++) {
        const int cur = t & 1;
        if (t + 1 < nkt) {
            load_stage(cur ^ 1, t + 1);
            CP_COMMIT();
            CP_WAIT(1);
        } else {
            CP_WAIT(0);
        }
        __syncthreads();

        const __nv_bfloat16* sAh = gsm + cur * GEMM_STG;
        const __nv_bfloat16* sAl = sAh + GEMM_ASZ;
        const __nv_bfloat16* sWh = sAh + 2 * GEMM_ASZ;
        const __nv_bfloat16* sWl = sAh + 3 * GEMM_ASZ;

#pragma unroll
        for (int ks = 0; ks < 2; ks++) {
            uint32_t ah[4][4], al[4][4], bh[4][2], bl[4][2];
            const int acol = ks * 16 + (lane >> 4) * 8;
            const int bcol = ks * 16 + ((lane >> 3) & 1) * 8;
#pragma unroll
            for (int mt = 0; mt < 4; mt++) {
                int r = wm * 64 + mt * 16 + (lane & 15);
                ldsm_x4(ah[mt], &sAh[r * SSTR + acol]);
                ldsm_x4(al[mt], &sAl[r * SSTR + acol]);
            }
#pragma unroll
            for (int nt = 0; nt < 4; nt++) {
                int r = wn * 32 + nt * 8 + (lane & 7);
                ldsm_x2(bh[nt], &sWh[r * SSTR + bcol]);
                ldsm_x2(bl[nt], &sWl[r * SSTR + bcol]);
            }
#pragma unroll
            for (int mt = 0; mt < 4; mt++)
#pragma unroll
                for (int nt = 0; nt < 4; nt++)
                    mma16816(acc[mt][nt], ah[mt], bh[nt]);
#pragma unroll
            for (int mt = 0; mt < 4; mt++)
#pragma unroll
                for (int nt = 0; nt < 4; nt++)
                    mma16816(acc[mt][nt], ah[mt], bl[nt]);
#pragma unroll
            for (int mt = 0; mt < 4; mt++)
#pragma unroll
                for (int nt = 0; nt < 4; nt++)
                    mma16816(acc[mt][nt], al[mt], bh[nt]);
        }
        __syncthreads();
    }

    if (EPI == 0) {
#pragma unroll
        for (int mt = 0; mt < 4; mt++) {
            int m = m0 + wm * 64 + mt * 16 + (lane >> 2);
#pragma unroll
            for (int nt = 0; nt < 4; nt++) {
                int n = n0 + wn * 32 + nt * 8 + (lane & 3) * 2;
                float2 bb = *(const float2*)&bias[n];
                float2 v0 = {acc[mt][nt][0] + bb.x, acc[mt][nt][1] + bb.y};
                float2 v1 = {acc[mt][nt][2] + bb.x, acc[mt][nt][3] + bb.y};
                *(float2*)&C[(size_t)m * Nc + n]       = v0;
                *(float2*)&C[(size_t)(m + 8) * Nc + n] = v1;
            }
        }
    } else {
        float* smf = (float*)gsm;
#pragma unroll
        for (int mt = 0; mt < 4; mt++) {
            int rl = wm * 64 + mt * 16 + (lane >> 2);
#pragma unroll
            for (int nt = 0; nt < 4; nt++) {
                int cl = wn * 32 + nt * 8 + (lane & 3) * 2;
                float2 v0 = {acc[mt][nt][0], acc[mt][nt][1]};
                float2 v1 = {acc[mt][nt][2], acc[mt][nt][3]};
                *(float2*)&smf[rl * ESTR + cl]       = v0;
                *(float2*)&smf[(rl + 8) * ESTR + cl] = v1;
            }
        }
        __syncthreads();

        const int b   = m0 >> 11;
        const int nt0 = m0 & (N_ - 1);

        if (n0 < 2 * D_) {
            const bool isq = (n0 < D_);
            const int cbase = isq ? n0 : (n0 - D_);
            __nv_bfloat16* dh = isq ? g_qh : g_kh;
            __nv_bfloat16* dl = isq ? g_ql : g_kl;
            const float qs = isq ? 0.125f : 1.0f;
            for (int f = tid; f < 8192; f += 256) {
                int r  = f >> 6;
                int c2 = (f & 63) * 2;
                int cg = cbase + c2;
                int h  = cg >> 6;
                int d  = cg & 63;
                int n  = nt0 + r;
                float2 x = *(const float2*)&smf[r * ESTR + c2];
                float2 p = *(const float2*)&smf[r * ESTR + (c2 ^ 32)];
                float2 cs = *(const float2*)&g_cosT[n * HD_ + d];
                float2 sn = *(const float2*)&g_sinT[n * HD_ + d];
                float sgn = (d < 32) ? -1.f : 1.f;
                float o0 = (x.x * cs.x + sgn * p.x * sn.x) * qs;
                float o1 = (x.y * cs.y + sgn * p.y * sn.y) * qs;
                uint32_t hh, ll;
                split2(o0, o1, hh, ll);
                size_t dst = ((size_t)(b * H_ + h) * N_ + n) * HD_ + d;
                *(uint32_t*)&dh[dst] = hh;
                *(uint32_t*)&dl[dst] = ll;
            }
        } else {
            const int cbase = n0 - 2 * D_;
            for (int f = tid; f < 8192; f += 256) {
                int c  = f >> 6;
                int np = (f & 63) * 2;
                int cg = cbase + c;
                int h  = cg >> 6;
                int d  = cg & 63;
                float v0 = smf[np * ESTR + c];
                float v1 = smf[(np + 1) * ESTR + c];
                uint32_t hh, ll;
                split2(v0, v1, hh, ll);
                size_t dst = ((size_t)(b * H_ + h) * HD_ + d) * N_ + nt0 + np;
                *(uint32_t*)&g_vh[dst] = hh;
                *(uint32_t*)&g_vl[dst] = ll;
            }
        }
    }
}

// ---------------------------------------------------------------------------
// Tensor-core flash attention — R13 macro-shape; K and V operands now loaded
// via ldmatrix x4 with direct scalar operand passing (no register repack).
// ---------------------------------------------------------------------------
#define QKS 72
#define VTS 136
#define A_QT   (128 * QKS)
#define A_KT   (128 * QKS)
#define A_VT   (64 * VTS)
#define A_STG  (2 * A_KT + 2 * A_VT)
#define A_SMEM ((2 * A_QT + 2 * A_STG) * 2)

__global__ __launch_bounds__(256, 1) void attn_mma_kernel()
{
    extern __shared__ __nv_bfloat16 smb[];
    __nv_bfloat16* sQh = smb;
    __nv_bfloat16* sQl = smb + A_QT;
    __nv_bfloat16* stage0 = smb + 2 * A_QT;

    const int tid  = threadIdx.x;
    const int lane = tid & 31;
    const int wid  = tid >> 5;
    const int w16  = wid * 16;
    const int bh   = blockIdx.y;
    const int b    = bh / H_;
    const int h    = bh % H_;
    const int q0   = blockIdx.x * 128;

    const __nv_bfloat16* qhb = g_qh + (size_t)bh * N_ * HD_;
    const __nv_bfloat16* qlb = g_ql + (size_t)bh * N_ * HD_;
    const __nv_bfloat16* khb = g_kh + (size_t)bh * N_ * HD_;
    const __nv_bfloat16* klb = g_kl + (size_t)bh * N_ * HD_;
    const __nv_bfloat16* vhb = g_vh + (size_t)bh * HD_ * N_;
    const __nv_bfloat16* vlb = g_vl + (size_t)bh * HD_ * N_;

    for (int f = tid; f < 1024; f += 256) {
        int row = f >> 3;
        int ch  = (f & 7) * 8;
        *(uint4*)&sQh[row * QKS + ch] = *(const uint4*)(qhb + (size_t)(q0 + row) * HD_ + ch);
        *(uint4*)&sQl[row * QKS + ch] = *(const uint4*)(qlb + (size_t)(q0 + row) * HD_ + ch);
    }

    auto load_stage = [&](int st, int kt) {
        __nv_bfloat16* base = stage0 + st * A_STG;
        const int k0 = kt * 128;
        for (int f = tid; f < 1024; f += 256) {
            int row = f >> 3;
            int ch  = (f & 7) * 8;
            size_t g = (size_t)(k0 + row) * HD_ + ch;
            int so = row * QKS + ch;
            cp16(base + so,        khb + g);
            cp16(base + A_KT + so, klb + g);
        }
        __nv_bfloat16* vb = base + 2 * A_KT;
        for (int f = tid; f < 1024; f += 256) {
            int d  = f >> 4;
            int ch = (f & 15) * 8;
            size_t g = (size_t)d * N_ + k0 + ch;
            int so = d * VTS + ch;
            cp16(vb + so,        vhb + g);
            cp16(vb + A_VT + so, vlb + g);
        }
    };

    float oacc[8][4];
#pragma unroll
    for (int ob = 0; ob < 8; ob++)
#pragma unroll
        for (int e = 0; e < 4; e++) oacc[ob][e] = 0.f;
    float m0 = -1e30f, m1 = -1e30f, l0 = 0.f, l1 = 0.f;

    load_stage(0, 0);
    CP_COMMIT();

    for (int kt = 0; kt < N_ / 128; kt++) {
        const int cur = kt & 1;
        if (kt + 1 < N_ / 128) {
            load_stage(cur ^ 1, kt + 1);
            CP_COMMIT();
            CP_WAIT(1);
        } else {
            CP_WAIT(0);
        }
        __syncthreads();

        const __nv_bfloat16* sKh = stage0 + cur * A_STG;
        const __nv_bfloat16* sKl = sKh + A_KT;
        const __nv_bfloat16* sVh = sKh + 2 * A_KT;
        const __nv_bfloat16* sVl = sVh + A_VT;

        // ---- S = Q @ K^T : x4 K loads, term-outer groups of 4 ----
        float sacc[16][4];
#pragma unroll
        for (int nb = 0; nb < 16; nb++)
#pragma unroll
            for (int e = 0; e < 4; e++) sacc[nb][e] = 0.f;

#pragma unroll
        for (int ks = 0; ks < 4; ks++) {
            uint32_t ah[4], al[4];
            const int acol = ks * 16 + (lane >> 4) * 8;
            ldsm_x4(ah, &sQh[(w16 + (lane & 15)) * QKS + acol]);
            ldsm_x4(al, &sQl[(w16 + (lane & 15)) * QKS + acol]);
#pragma unroll
            for (int g = 0; g < 4; g++) {        // nb = 4g..4g+3
                uint32_t kh4[2][4], kl4[2][4];
#pragma unroll
                for (int p = 0; p < 2; p++) {
                    int r = (g * 2 + p) * 16 + (lane & 15);
                    ldsm_x4(kh4[p], &sKh[r * QKS + acol]);
                    ldsm_x4(kl4[p], &sKl[r * QKS + acol]);
                }
#pragma unroll
                for (int q = 0; q < 4; q++)
                    mma16816s(sacc[g * 4 + q], ah, kh4[q >> 1][q & 1], kh4[q >> 1][(q & 1) + 2]);
#pragma unroll
                for (int q = 0; q < 4; q++)
                    mma16816s(sacc[g * 4 + q], ah, kl4[q >> 1][q & 1], kl4[q >> 1][(q & 1) + 2]);
#pragma unroll
                for (int q = 0; q < 4; q++)
                    mma16816s(sacc[g * 4 + q], al, kh4[q >> 1][q & 1], kh4[q >> 1][(q & 1) + 2]);
            }
        }

        // ---- online softmax ----
        float mx0 = -1e30f, mx1 = -1e30f;
#pragma unroll
        for (int nb = 0; nb < 16; nb++) {
            mx0 = fmaxf(mx0, fmaxf(sacc[nb][0], sacc[nb][1]));
            mx1 = fmaxf(mx1, fmaxf(sacc[nb][2], sacc[nb][3]));
        }
        mx0 = fmaxf(mx0, __shfl_xor_sync(0xffffffffu, mx0, 1));
        mx0 = fmaxf(mx0, __shfl_xor_sync(0xffffffffu, mx0, 2));
        mx1 = fmaxf(mx1, __shfl_xor_sync(0xffffffffu, mx1, 1));
        mx1 = fmaxf(mx1, __shfl_xor_sync(0xffffffffu, mx1, 2));

        float mn0 = fmaxf(m0, mx0);
        float mn1 = fmaxf(m1, mx1);
        float cr0 = __expf(m0 - mn0);
        float cr1 = __expf(m1 - mn1);
        m0 = mn0; m1 = mn1;

        float rs0 = 0.f, rs1 = 0.f;
#pragma unroll
        for (int nb = 0; nb < 16; nb++) {
            sacc[nb][0] = __expf(sacc[nb][0] - mn0);
            sacc[nb][1] = __expf(sacc[nb][1] - mn0);
            sacc[nb][2] = __expf(sacc[nb][2] - mn1);
            sacc[nb][3] = __expf(sacc[nb][3] - mn1);
            rs0 += sacc[nb][0] + sacc[nb][1];
            rs1 += sacc[nb][2] + sacc[nb][3];
        }
        rs0 += __shfl_xor_sync(0xffffffffu, rs0, 1);
        rs0 += __shfl_xor_sync(0xffffffffu, rs0, 2);
        rs1 += __shfl_xor_sync(0xffffffffu, rs1, 1);
        rs1 += __shfl_xor_sync(0xffffffffu, rs1, 2);
        l0 = l0 * cr0 + rs0;
        l1 = l1 * cr1 + rs1;
#pragma unroll
        for (int ob = 0; ob < 8; ob++) {
            oacc[ob][0] *= cr0; oacc[ob][1] *= cr0;
            oacc[ob][2] *= cr1; oacc[ob][3] *= cr1;
        }

        // ---- pack P into bf16 hi/lo A fragments ----
        uint32_t pah[8][4], pal[8][4];
#pragma unroll
        for (int kb = 0; kb < 8; kb++) {
            split2(sacc[2 * kb][0],     sacc[2 * kb][1],     pah[kb][0], pal[kb][0]);
            split2(sacc[2 * kb][2],     sacc[2 * kb][3],     pah[kb][1], pal[kb][1]);
            split2(sacc[2 * kb + 1][0], sacc[2 * kb + 1][1], pah[kb][2], pal[kb][2]);
            split2(sacc[2 * kb + 1][2], sacc[2 * kb + 1][3], pah[kb][3], pal[kb][3]);
        }

        // ---- O += P @ V : x4 V loads, kb-outer, term-outer over 8 oacc ----
#pragma unroll
        for (int kb = 0; kb < 8; kb++) {
            const int bcol = kb * 16 + (lane >> 4) * 8;
            uint32_t vh4[4][4], vl4[4][4];
#pragma unroll
            for (int op = 0; op < 4; op++) {
                int r = op * 16 + (lane & 15);
                ldsm_x4(vh4[op], &sVh[r * VTS + bcol]);
                ldsm_x4(vl4[op], &sVl[r * VTS + bcol]);
            }
#pragma unroll
            for (int ob = 0; ob < 8; ob++)
                mma16816s(oacc[ob], pah[kb], vh4[ob >> 1][ob & 1], vh4[ob >> 1][(ob & 1) + 2]);
#pragma unroll
            for (int ob = 0; ob < 8; ob++)
                mma16816s(oacc[ob], pah[kb], vl4[ob >> 1][ob & 1], vl4[ob >> 1][(ob & 1) + 2]);
#pragma unroll
            for (int ob = 0; ob < 8; ob++)
                mma16816s(oacc[ob], pal[kb], vh4[ob >> 1][ob & 1], vh4[ob >> 1][(ob & 1) + 2]);
        }
        __syncthreads();
    }

    // ---- epilogue: normalize, split to bf16 hi/lo for the out-proj GEMM ----
    float inv0 = 1.f / l0;
    float inv1 = 1.f / l1;
    const int r0 = q0 + w16 + (lane >> 2);
#pragma unroll
    for (int ob = 0; ob < 8; ob++) {
        int col = h * HD_ + ob * 8 + (lane & 3) * 2;
        size_t i0 = (size_t)(b * N_ + r0) * D_ + col;
        size_t i1 = (size_t)(b * N_ + r0 + 8) * D_ + col;
        uint32_t hh, ll;
        split2(oacc[ob][0] * inv0, oacc[ob][1] * inv0, hh, ll);
        *(uint32_t*)&g_aoh[i0] = hh;
        *(uint32_t*)&g_aol[i0] = ll;
        split2(oacc[ob][2] * inv1, oacc[ob][3] * inv1, hh, ll);
        *(uint32_t*)&g_aoh[i1] = hh;
        *(uint32_t*)&g_aol[i1] = ll;
    }
}

// ---------------------------------------------------------------------------
extern "C" void kernel_launch(void* const* d_in, const int* in_sizes, int n_in,
                              void* d_out, int out_size)
{
    const float* x     = (const float*)d_in[0];
    const float* pe    = (const float*)d_in[1];
    const float* Wqkv  = (const float*)d_in[2];
    const float* Wproj = (const float*)d_in[3];
    const float* bproj = (const float*)d_in[4];
    float* out = (float*)d_out;

    __nv_bfloat16 *xh, *xl, *wqh, *wql, *aoh, *aol, *wph, *wpl;
    cudaGetSymbolAddress((void**)&xh,  g_xh);
    cudaGetSymbolAddress((void**)&xl,  g_xl);
    cudaGetSymbolAddress((void**)&wqh, g_wqh);
    cudaGetSymbolAddress((void**)&wql, g_wql);
    cudaGetSymbolAddress((void**)&aoh, g_aoh);
    cudaGetSymbolAddress((void**)&aol, g_aol);
    cudaGetSymbolAddress((void**)&wph, g_wph);
    cudaGetSymbolAddress((void**)&wpl, g_wpl);

    const int M = B_ * N_;           // 4096

    // 0) fused prologue: all splits + sincos in one launch
    {
        int blocks = (PRO_TOTAL + 255) / 256;
        prologue_kernel<<<blocks, 256>>>((const float4*)x, (const float4*)Wqkv,
                                         (const float4*)Wproj, pe);
    }
    // 1) QKV projection with fused RoPE + split + V-transpose epilogue
    {
        cudaFuncSetAttribute(gemm_mma_kernel<1>,
                             cudaFuncAttributeMaxDynamicSharedMemorySize, GEMM_SMEM);
        dim3 grid(QKVSTRIDE / 128, M / 128);
        gemm_mma_kernel<1><<<grid, 256, GEMM_SMEM>>>(xh, xl, wqh, wql, nullptr, nullptr,
                                                     M, QKVSTRIDE, D_);
    }
    // 2) Attention
    {
        cudaFuncSetAttribute(attn_mma_kernel,
                             cudaFuncAttributeMaxDynamicSharedMemorySize, A_SMEM);
        dim3 grid(N_ / 128, BH_);
        attn_mma_kernel<<<grid, 256, A_SMEM>>>();
    }
    // 3) output projection
    {
        cudaFuncSetAttribute(gemm_mma_kernel<0>,
                             cudaFuncAttributeMaxDynamicSharedMemorySize, GEMM_SMEM);
        dim3 grid(D_ / 128, M / 128);
        gemm_mma_kernel<0><<<grid, 256, GEMM_SMEM>>>(aoh, aol, wph, wpl, bproj, out,
                                                     M, D_, D_);
    }
}

// round 15
// speedup vs baseline: 1.0580x; 1.0580x over previous
#include <cuda_runtime.h>
#include <cuda_bf16.h>
#include <cstdint>
#include <math.h>

#define B_ 2
#define N_ 2048
#define D_ 768
#define H_ 12
#define HD_ 64
#define QKVSTRIDE (3 * D_)   // 2304
#define BH_ (B_ * H_)        // 24

// ---------------- scratch (allocation-free) ----------------
__device__ __nv_bfloat16 g_xh[(size_t)B_ * N_ * D_];
__device__ __nv_bfloat16 g_xl[(size_t)B_ * N_ * D_];
__device__ __nv_bfloat16 g_wqh[(size_t)QKVSTRIDE * D_];
__device__ __nv_bfloat16 g_wql[(size_t)QKVSTRIDE * D_];
__device__ __nv_bfloat16 g_aoh[(size_t)B_ * N_ * D_];
__device__ __nv_bfloat16 g_aol[(size_t)B_ * N_ * D_];
__device__ __nv_bfloat16 g_wph[(size_t)D_ * D_];
__device__ __nv_bfloat16 g_wpl[(size_t)D_ * D_];
__device__ __nv_bfloat16 g_qh[(size_t)BH_ * N_ * HD_];
__device__ __nv_bfloat16 g_ql[(size_t)BH_ * N_ * HD_];
__device__ __nv_bfloat16 g_kh[(size_t)BH_ * N_ * HD_];
__device__ __nv_bfloat16 g_kl[(size_t)BH_ * N_ * HD_];
__device__ __nv_bfloat16 g_vh[(size_t)BH_ * HD_ * N_];  // [bh][d][n]
__device__ __nv_bfloat16 g_vl[(size_t)BH_ * HD_ * N_];
__device__ float g_cosT[(size_t)N_ * HD_];
__device__ float g_sinT[(size_t)N_ * HD_];

// ---------------- helpers ----------------
__device__ __forceinline__ void ldsm_x4(uint32_t* r, const void* p) {
    uint32_t a = (uint32_t)__cvta_generic_to_shared(p);
    asm volatile("ldmatrix.sync.aligned.m8n8.x4.shared.b16 {%0,%1,%2,%3}, [%4];"
                 : "=r"(r[0]), "=r"(r[1]), "=r"(r[2]), "=r"(r[3]) : "r"(a));
}
__device__ __forceinline__ void ldsm_x2(uint32_t* r, const void* p) {
    uint32_t a = (uint32_t)__cvta_generic_to_shared(p);
    asm volatile("ldmatrix.sync.aligned.m8n8.x2.shared.b16 {%0,%1}, [%2];"
                 : "=r"(r[0]), "=r"(r[1]) : "r"(a));
}
__device__ __forceinline__ void mma16816(float* c, const uint32_t* a, const uint32_t* b) {
    asm volatile(
        "mma.sync.aligned.m16n8k16.row.col.f32.bf16.bf16.f32 "
        "{%0,%1,%2,%3}, {%4,%5,%6,%7}, {%8,%9}, {%0,%1,%2,%3};"
        : "+f"(c[0]), "+f"(c[1]), "+f"(c[2]), "+f"(c[3])
        : "r"(a[0]), "r"(a[1]), "r"(a[2]), "r"(a[3]), "r"(b[0]), "r"(b[1]));
}
__device__ __forceinline__ void split2(float a, float b, uint32_t& h, uint32_t& l) {
    __nv_bfloat16 ha = __float2bfloat16(a), hb = __float2bfloat16(b);
    __nv_bfloat16 la = __float2bfloat16(a - __bfloat162float(ha));
    __nv_bfloat16 lb = __float2bfloat16(b - __bfloat162float(hb));
    h = (uint32_t)*(uint16_t*)&ha | ((uint32_t)*(uint16_t*)&hb << 16);
    l = (uint32_t)*(uint16_t*)&la | ((uint32_t)*(uint16_t*)&lb << 16);
}
__device__ __forceinline__ void cp16(void* s, const void* g) {
    uint32_t sa = (uint32_t)__cvta_generic_to_shared(s);
    asm volatile("cp.async.ca.shared.global [%0], [%1], 16;" :: "r"(sa), "l"(g));
}
#define CP_COMMIT() asm volatile("cp.async.commit_group;" ::: "memory")
#define CP_WAIT(n)  asm volatile("cp.async.wait_group %0;" :: "n"(n) : "memory")

// ---------------------------------------------------------------------------
// fused prologue: x split | Wqkv split | Wproj split | sincos table
// ---------------------------------------------------------------------------
#define NX4 ((B_ * N_ * D_) / 4)          // 786432
#define NW4 ((QKVSTRIDE * D_) / 4)        // 442368
#define NP4 ((D_ * D_) / 4)               // 147456
#define NS_ (N_ * HD_)                    // 131072
#define PRO_TOTAL (NX4 + NW4 + NP4 + NS_)

__global__ void prologue_kernel(const float4* __restrict__ x,
                                const float4* __restrict__ wq,
                                const float4* __restrict__ wp,
                                const float* __restrict__ pe)
{
    int i = blockIdx.x * blockDim.x + threadIdx.x;
    if (i < NX4) {
        float4 v = x[i];
        uint2 ho, lo;
        split2(v.x, v.y, ho.x, lo.x);
        split2(v.z, v.w, ho.y, lo.y);
        ((uint2*)g_xh)[i] = ho; ((uint2*)g_xl)[i] = lo;
    } else if (i < NX4 + NW4) {
        int j = i - NX4;
        float4 v = wq[j];
        uint2 ho, lo;
        split2(v.x, v.y, ho.x, lo.x);
        split2(v.z, v.w, ho.y, lo.y);
        ((uint2*)g_wqh)[j] = ho; ((uint2*)g_wql)[j] = lo;
    } else if (i < NX4 + NW4 + NP4) {
        int j = i - NX4 - NW4;
        float4 v = wp[j];
        uint2 ho, lo;
        split2(v.x, v.y, ho.x, lo.x);
        split2(v.z, v.w, ho.y, lo.y);
        ((uint2*)g_wph)[j] = ho; ((uint2*)g_wpl)[j] = lo;
    } else if (i < PRO_TOTAL) {
        int j = i - NX4 - NW4 - NP4;
        float s, c;
        sincosf(pe[j], &s, &c);
        g_sinT[j] = s;
        g_cosT[j] = c;
    }
}

// ---------------------------------------------------------------------------
// HMMA GEMM — R10 proven mainloop. EPI=0: plain+bias. EPI=1: fused RoPE +
// hi/lo split + V-transpose epilogue (QKV projection).
// ---------------------------------------------------------------------------
#define SSTR 40
#define GEMM_ASZ (128 * SSTR)
#define GEMM_STG (4 * GEMM_ASZ)
#define GEMM_SMEM (2 * GEMM_STG * 2)   // 81920 bytes
#define ESTR 132

template <int EPI>
__global__ __launch_bounds__(256) void gemm_mma_kernel(
    const __nv_bfloat16* __restrict__ Ah, const __nv_bfloat16* __restrict__ Al,
    const __nv_bfloat16* __restrict__ Wh, const __nv_bfloat16* __restrict__ Wl,
    const float* __restrict__ bias, float* __restrict__ C,
    int M, int Nc, int K)
{
    extern __shared__ __nv_bfloat16 gsm[];

    const int tid  = threadIdx.x;
    const int lane = tid & 31;
    const int wid  = tid >> 5;
    const int wm   = wid & 1;
    const int wn   = wid >> 1;
    const int m0   = blockIdx.y * 128;
    const int n0   = blockIdx.x * 128;

    float acc[4][4][4];
#pragma unroll
    for (int mt = 0; mt < 4; mt++)
#pragma unroll
        for (int nt = 0; nt < 4; nt++)
#pragma unroll
            for (int e = 0; e < 4; e++) acc[mt][nt][e] = 0.f;

    const int nkt = K / 32;

    auto load_stage = [&](int st, int t) {
        __nv_bfloat16* base = gsm + st * GEMM_STG;
        const int kk = t * 32;
        for (int f = tid; f < 512; f += 256) {
            int row = f >> 2;
            int ch  = (f & 3) * 8;
            size_t ga = (size_t)(m0 + row) * K + kk + ch;
            size_t gw = (size_t)(n0 + row) * K + kk + ch;
            int so = row * SSTR + ch;
            cp16(base + so,                Ah + ga);
            cp16(base + GEMM_ASZ + so,     Al + ga);
            cp16(base + 2 * GEMM_ASZ + so, Wh + gw);
            cp16(base + 3 * GEMM_ASZ + so, Wl + gw);
        }
    };

    load_stage(0, 0);
    CP_COMMIT();

    for (int t = 0; t < nkt; t++) {
        const int cur = t & 1;
        if (t + 1 < nkt) {
            load_stage(cur ^ 1, t + 1);
            CP_COMMIT();
            CP_WAIT(1);
        } else {
            CP_WAIT(0);
        }
        __syncthreads();

        const __nv_bfloat16* sAh = gsm + cur * GEMM_STG;
        const __nv_bfloat16* sAl = sAh + GEMM_ASZ;
        const __nv_bfloat16* sWh = sAh + 2 * GEMM_ASZ;
        const __nv_bfloat16* sWl = sAh + 3 * GEMM_ASZ;

#pragma unroll
        for (int ks = 0; ks < 2; ks++) {
            uint32_t ah[4][4], al[4][4], bh[4][2], bl[4][2];
            const int acol = ks * 16 + (lane >> 4) * 8;
            const int bcol = ks * 16 + ((lane >> 3) & 1) * 8;
#pragma unroll
            for (int mt = 0; mt < 4; mt++) {
                int r = wm * 64 + mt * 16 + (lane & 15);
                ldsm_x4(ah[mt], &sAh[r * SSTR + acol]);
                ldsm_x4(al[mt], &sAl[r * SSTR + acol]);
            }
#pragma unroll
            for (int nt = 0; nt < 4; nt++) {
                int r = wn * 32 + nt * 8 + (lane & 7);
                ldsm_x2(bh[nt], &sWh[r * SSTR + bcol]);
                ldsm_x2(bl[nt], &sWl[r * SSTR + bcol]);
            }
#pragma unroll
            for (int mt = 0; mt < 4; mt++)
#pragma unroll
                for (int nt = 0; nt < 4; nt++)
                    mma16816(acc[mt][nt], ah[mt], bh[nt]);
#pragma unroll
            for (int mt = 0; mt < 4; mt++)
#pragma unroll
                for (int nt = 0; nt < 4; nt++)
                    mma16816(acc[mt][nt], ah[mt], bl[nt]);
#pragma unroll
            for (int mt = 0; mt < 4; mt++)
#pragma unroll
                for (int nt = 0; nt < 4; nt++)
                    mma16816(acc[mt][nt], al[mt], bh[nt]);
        }
        __syncthreads();
    }

    if (EPI == 0) {
#pragma unroll
        for (int mt = 0; mt < 4; mt++) {
            int m = m0 + wm * 64 + mt * 16 + (lane >> 2);
#pragma unroll
            for (int nt = 0; nt < 4; nt++) {
                int n = n0 + wn * 32 + nt * 8 + (lane & 3) * 2;
                float2 bb = *(const float2*)&bias[n];
                float2 v0 = {acc[mt][nt][0] + bb.x, acc[mt][nt][1] + bb.y};
                float2 v1 = {acc[mt][nt][2] + bb.x, acc[mt][nt][3] + bb.y};
                *(float2*)&C[(size_t)m * Nc + n]       = v0;
                *(float2*)&C[(size_t)(m + 8) * Nc + n] = v1;
            }
        }
    } else {
        float* smf = (float*)gsm;
#pragma unroll
        for (int mt = 0; mt < 4; mt++) {
            int rl = wm * 64 + mt * 16 + (lane >> 2);
#pragma unroll
            for (int nt = 0; nt < 4; nt++) {
                int cl = wn * 32 + nt * 8 + (lane & 3) * 2;
                float2 v0 = {acc[mt][nt][0], acc[mt][nt][1]};
                float2 v1 = {acc[mt][nt][2], acc[mt][nt][3]};
                *(float2*)&smf[rl * ESTR + cl]       = v0;
                *(float2*)&smf[(rl + 8) * ESTR + cl] = v1;
            }
        }
        __syncthreads();

        const int b   = m0 >> 11;
        const int nt0 = m0 & (N_ - 1);

        if (n0 < 2 * D_) {
            const bool isq = (n0 < D_);
            const int cbase = isq ? n0 : (n0 - D_);
            __nv_bfloat16* dh = isq ? g_qh : g_kh;
            __nv_bfloat16* dl = isq ? g_ql : g_kl;
            const float qs = isq ? 0.125f : 1.0f;
            for (int f = tid; f < 8192; f += 256) {
                int r  = f >> 6;
                int c2 = (f & 63) * 2;
                int cg = cbase + c2;
                int h  = cg >> 6;
                int d  = cg & 63;
                int n  = nt0 + r;
                float2 x = *(const float2*)&smf[r * ESTR + c2];
                float2 p = *(const float2*)&smf[r * ESTR + (c2 ^ 32)];
                float2 cs = *(const float2*)&g_cosT[n * HD_ + d];
                float2 sn = *(const float2*)&g_sinT[n * HD_ + d];
                float sgn = (d < 32) ? -1.f : 1.f;
                float o0 = (x.x * cs.x + sgn * p.x * sn.x) * qs;
                float o1 = (x.y * cs.y + sgn * p.y * sn.y) * qs;
                uint32_t hh, ll;
                split2(o0, o1, hh, ll);
                size_t dst = ((size_t)(b * H_ + h) * N_ + n) * HD_ + d;
                *(uint32_t*)&dh[dst] = hh;
                *(uint32_t*)&dl[dst] = ll;
            }
        } else {
            const int cbase = n0 - 2 * D_;
            for (int f = tid; f < 8192; f += 256) {
                int c  = f >> 6;
                int np = (f & 63) * 2;
                int cg = cbase + c;
                int h  = cg >> 6;
                int d  = cg & 63;
                float v0 = smf[np * ESTR + c];
                float v1 = smf[(np + 1) * ESTR + c];
                uint32_t hh, ll;
                split2(v0, v1, hh, ll);
                size_t dst = ((size_t)(b * H_ + h) * HD_ + d) * N_ + nt0 + np;
                *(uint32_t*)&g_vh[dst] = hh;
                *(uint32_t*)&g_vl[dst] = ll;
            }
        }
    }
}

// ---------------------------------------------------------------------------
// Tensor-core flash attention — R13/R10 proven (128-key tiles, 256 thr,
// 2-stage cp.async, ldsm_x2 operands, term-outer MMA ordering, fused bf16
// hi/lo epilogue).
// ---------------------------------------------------------------------------
#define QKS 72
#define VTS 136
#define A_QT   (128 * QKS)
#define A_KT   (128 * QKS)
#define A_VT   (64 * VTS)
#define A_STG  (2 * A_KT + 2 * A_VT)
#define A_SMEM ((2 * A_QT + 2 * A_STG) * 2)

__global__ __launch_bounds__(256, 1) void attn_mma_kernel()
{
    extern __shared__ __nv_bfloat16 smb[];
    __nv_bfloat16* sQh = smb;
    __nv_bfloat16* sQl = smb + A_QT;
    __nv_bfloat16* stage0 = smb + 2 * A_QT;

    const int tid  = threadIdx.x;
    const int lane = tid & 31;
    const int wid  = tid >> 5;
    const int w16  = wid * 16;
    const int bh   = blockIdx.y;
    const int b    = bh / H_;
    const int h    = bh % H_;
    const int q0   = blockIdx.x * 128;

    const __nv_bfloat16* qhb = g_qh + (size_t)bh * N_ * HD_;
    const __nv_bfloat16* qlb = g_ql + (size_t)bh * N_ * HD_;
    const __nv_bfloat16* khb = g_kh + (size_t)bh * N_ * HD_;
    const __nv_bfloat16* klb = g_kl + (size_t)bh * N_ * HD_;
    const __nv_bfloat16* vhb = g_vh + (size_t)bh * HD_ * N_;
    const __nv_bfloat16* vlb = g_vl + (size_t)bh * HD_ * N_;

    for (int f = tid; f < 1024; f += 256) {
        int row = f >> 3;
        int ch  = (f & 7) * 8;
        *(uint4*)&sQh[row * QKS + ch] = *(const uint4*)(qhb + (size_t)(q0 + row) * HD_ + ch);
        *(uint4*)&sQl[row * QKS + ch] = *(const uint4*)(qlb + (size_t)(q0 + row) * HD_ + ch);
    }

    auto load_stage = [&](int st, int kt) {
        __nv_bfloat16* base = stage0 + st * A_STG;
        const int k0 = kt * 128;
        for (int f = tid; f < 1024; f += 256) {
            int row = f >> 3;
            int ch  = (f & 7) * 8;
            size_t g = (size_t)(k0 + row) * HD_ + ch;
            int so = row * QKS + ch;
            cp16(base + so,        khb + g);
            cp16(base + A_KT + so, klb + g);
        }
        __nv_bfloat16* vb = base + 2 * A_KT;
        for (int f = tid; f < 1024; f += 256) {
            int d  = f >> 4;
            int ch = (f & 15) * 8;
            size_t g = (size_t)d * N_ + k0 + ch;
            int so = d * VTS + ch;
            cp16(vb + so,        vhb + g);
            cp16(vb + A_VT + so, vlb + g);
        }
    };

    float oacc[8][4];
#pragma unroll
    for (int ob = 0; ob < 8; ob++)
#pragma unroll
        for (int e = 0; e < 4; e++) oacc[ob][e] = 0.f;
    float m0 = -1e30f, m1 = -1e30f, l0 = 0.f, l1 = 0.f;

    load_stage(0, 0);
    CP_COMMIT();

    for (int kt = 0; kt < N_ / 128; kt++) {
        const int cur = kt & 1;
        if (kt + 1 < N_ / 128) {
            load_stage(cur ^ 1, kt + 1);
            CP_COMMIT();
            CP_WAIT(1);
        } else {
            CP_WAIT(0);
        }
        __syncthreads();

        const __nv_bfloat16* sKh = stage0 + cur * A_STG;
        const __nv_bfloat16* sKl = sKh + A_KT;
        const __nv_bfloat16* sVh = sKh + 2 * A_KT;
        const __nv_bfloat16* sVl = sVh + A_VT;

        // ---- S = Q @ K^T : groups of 4 accumulators, term-outer ----
        float sacc[16][4];
#pragma unroll
        for (int nb = 0; nb < 16; nb++)
#pragma unroll
            for (int e = 0; e < 4; e++) sacc[nb][e] = 0.f;

#pragma unroll
        for (int ks = 0; ks < 4; ks++) {
            uint32_t ah[4], al[4];
            const int acol = ks * 16 + (lane >> 4) * 8;
            ldsm_x4(ah, &sQh[(w16 + (lane & 15)) * QKS + acol]);
            ldsm_x4(al, &sQl[(w16 + (lane & 15)) * QKS + acol]);
            const int bcol = ks * 16 + ((lane >> 3) & 1) * 8;
#pragma unroll
            for (int g = 0; g < 4; g++) {
                uint32_t bhf[4][2], blf[4][2];
#pragma unroll
                for (int q = 0; q < 4; q++) {
                    int nb = g * 4 + q;
                    ldsm_x2(bhf[q], &sKh[(nb * 8 + (lane & 7)) * QKS + bcol]);
                    ldsm_x2(blf[q], &sKl[(nb * 8 + (lane & 7)) * QKS + bcol]);
                }
#pragma unroll
                for (int q = 0; q < 4; q++) mma16816(sacc[g * 4 + q], ah, bhf[q]);
#pragma unroll
                for (int q = 0; q < 4; q++) mma16816(sacc[g * 4 + q], ah, blf[q]);
#pragma unroll
                for (int q = 0; q < 4; q++) mma16816(sacc[g * 4 + q], al, bhf[q]);
            }
        }

        // ---- online softmax ----
        float mx0 = -1e30f, mx1 = -1e30f;
#pragma unroll
        for (int nb = 0; nb < 16; nb++) {
            mx0 = fmaxf(mx0, fmaxf(sacc[nb][0], sacc[nb][1]));
            mx1 = fmaxf(mx1, fmaxf(sacc[nb][2], sacc[nb][3]));
        }
        mx0 = fmaxf(mx0, __shfl_xor_sync(0xffffffffu, mx0, 1));
        mx0 = fmaxf(mx0, __shfl_xor_sync(0xffffffffu, mx0, 2));
        mx1 = fmaxf(mx1, __shfl_xor_sync(0xffffffffu, mx1, 1));
        mx1 = fmaxf(mx1, __shfl_xor_sync(0xffffffffu, mx1, 2));

        float mn0 = fmaxf(m0, mx0);
        float mn1 = fmaxf(m1, mx1);
        float cr0 = __expf(m0 - mn0);
        float cr1 = __expf(m1 - mn1);
        m0 = mn0; m1 = mn1;

        float rs0 = 0.f, rs1 = 0.f;
#pragma unroll
        for (int nb = 0; nb < 16; nb++) {
            sacc[nb][0] = __expf(sacc[nb][0] - mn0);
            sacc[nb][1] = __expf(sacc[nb][1] - mn0);
            sacc[nb][2] = __expf(sacc[nb][2] - mn1);
            sacc[nb][3] = __expf(sacc[nb][3] - mn1);
            rs0 += sacc[nb][0] + sacc[nb][1];
            rs1 += sacc[nb][2] + sacc[nb][3];
        }
        rs0 += __shfl_xor_sync(0xffffffffu, rs0, 1);
        rs0 += __shfl_xor_sync(0xffffffffu, rs0, 2);
        rs1 += __shfl_xor_sync(0xffffffffu, rs1, 1);
        rs1 += __shfl_xor_sync(0xffffffffu, rs1, 2);
        l0 = l0 * cr0 + rs0;
        l1 = l1 * cr1 + rs1;
#pragma unroll
        for (int ob = 0; ob < 8; ob++) {
            oacc[ob][0] *= cr0; oacc[ob][1] *= cr0;
            oacc[ob][2] *= cr1; oacc[ob][3] *= cr1;
        }

        // ---- pack P into bf16 hi/lo A fragments ----
        uint32_t pah[8][4], pal[8][4];
#pragma unroll
        for (int kb = 0; kb < 8; kb++) {
            split2(sacc[2 * kb][0],     sacc[2 * kb][1],     pah[kb][0], pal[kb][0]);
            split2(sacc[2 * kb][2],     sacc[2 * kb][3],     pah[kb][1], pal[kb][1]);
            split2(sacc[2 * kb + 1][0], sacc[2 * kb + 1][1], pah[kb][2], pal[kb][2]);
            split2(sacc[2 * kb + 1][2], sacc[2 * kb + 1][3], pah[kb][3], pal[kb][3]);
        }

        // ---- O += P @ V : kb-outer, term-outer over 8 oacc ----
#pragma unroll
        for (int kb = 0; kb < 8; kb++) {
            const int bcol = kb * 16 + ((lane >> 3) & 1) * 8;
            uint32_t vhf[8][2], vlf[8][2];
#pragma unroll
            for (int ob = 0; ob < 8; ob++) {
                ldsm_x2(vhf[ob], &sVh[(ob * 8 + (lane & 7)) * VTS + bcol]);
                ldsm_x2(vlf[ob], &sVl[(ob * 8 + (lane & 7)) * VTS + bcol]);
            }
#pragma unroll
            for (int ob = 0; ob < 8; ob++) mma16816(oacc[ob], pah[kb], vhf[ob]);
#pragma unroll
            for (int ob = 0; ob < 8; ob++) mma16816(oacc[ob], pah[kb], vlf[ob]);
#pragma unroll
            for (int ob = 0; ob < 8; ob++) mma16816(oacc[ob], pal[kb], vhf[ob]);
        }
        __syncthreads();
    }

    // ---- epilogue: normalize, split to bf16 hi/lo for the out-proj GEMM ----
    float inv0 = 1.f / l0;
    float inv1 = 1.f / l1;
    const int r0 = q0 + w16 + (lane >> 2);
#pragma unroll
    for (int ob = 0; ob < 8; ob++) {
        int col = h * HD_ + ob * 8 + (lane & 3) * 2;
        size_t i0 = (size_t)(b * N_ + r0) * D_ + col;
        size_t i1 = (size_t)(b * N_ + r0 + 8) * D_ + col;
        uint32_t hh, ll;
        split2(oacc[ob][0] * inv0, oacc[ob][1] * inv0, hh, ll);
        *(uint32_t*)&g_aoh[i0] = hh;
        *(uint32_t*)&g_aol[i0] = ll;
        split2(oacc[ob][2] * inv1, oacc[ob][3] * inv1, hh, ll);
        *(uint32_t*)&g_aoh[i1] = hh;
        *(uint32_t*)&g_aol[i1] = ll;
    }
}

// ---------------------------------------------------------------------------
extern "C" void kernel_launch(void* const* d_in, const int* in_sizes, int n_in,
                              void* d_out, int out_size)
{
    const float* x     = (const float*)d_in[0];
    const float* pe    = (const float*)d_in[1];
    const float* Wqkv  = (const float*)d_in[2];
    const float* Wproj = (const float*)d_in[3];
    const float* bproj = (const float*)d_in[4];
    float* out = (float*)d_out;

    __nv_bfloat16 *xh, *xl, *wqh, *wql, *aoh, *aol, *wph, *wpl;
    cudaGetSymbolAddress((void**)&xh,  g_xh);
    cudaGetSymbolAddress((void**)&xl,  g_xl);
    cudaGetSymbolAddress((void**)&wqh, g_wqh);
    cudaGetSymbolAddress((void**)&wql, g_wql);
    cudaGetSymbolAddress((void**)&aoh, g_aoh);
    cudaGetSymbolAddress((void**)&aol, g_aol);
    cudaGetSymbolAddress((void**)&wph, g_wph);
    cudaGetSymbolAddress((void**)&wpl, g_wpl);

    const int M = B_ * N_;           // 4096

    // 0) fused prologue: all splits + sincos in one launch
    {
        int blocks = (PRO_TOTAL + 255) / 256;
        prologue_kernel<<<blocks, 256>>>((const float4*)x, (const float4*)Wqkv,
                                         (const float4*)Wproj, pe);
    }
    // 1) QKV projection with fused RoPE + split + V-transpose epilogue
    {
        cudaFuncSetAttribute(gemm_mma_kernel<1>,
                             cudaFuncAttributeMaxDynamicSharedMemorySize, GEMM_SMEM);
        dim3 grid(QKVSTRIDE / 128, M / 128);
        gemm_mma_kernel<1><<<grid, 256, GEMM_SMEM>>>(xh, xl, wqh, wql, nullptr, nullptr,
                                                     M, QKVSTRIDE, D_);
    }
    // 2) Attention (R13 proven)
    {
        cudaFuncSetAttribute(attn_mma_kernel,
                             cudaFuncAttributeMaxDynamicSharedMemorySize, A_SMEM);
        dim3 grid(N_ / 128, BH_);
        attn_mma_kernel<<<grid, 256, A_SMEM>>>();
    }
    // 3) output projection
    {
        cudaFuncSetAttribute(gemm_mma_kernel<0>,
                             cudaFuncAttributeMaxDynamicSharedMemorySize, GEMM_SMEM);
        dim3 grid(D_ / 128, M / 128);
        gemm_mma_kernel<0><<<grid, 256, GEMM_SMEM>>>(aoh, aol, wph, wpl, bproj, out,
                                                     M, D_, D_);
    }
}

// round 16
// speedup vs baseline: 1.0775x; 1.0185x over previous
#include <cuda_runtime.h>
#include <cuda_bf16.h>
#include <cstdint>
#include <math.h>

#define B_ 2
#define N_ 2048
#define D_ 768
#define H_ 12
#define HD_ 64
#define QKVSTRIDE (3 * D_)   // 2304
#define BH_ (B_ * H_)        // 24

// ---------------- scratch (allocation-free) ----------------
__device__ __nv_bfloat16 g_xh[(size_t)B_ * N_ * D_];
__device__ __nv_bfloat16 g_xl[(size_t)B_ * N_ * D_];
__device__ __nv_bfloat16 g_wqh[(size_t)QKVSTRIDE * D_];
__device__ __nv_bfloat16 g_wql[(size_t)QKVSTRIDE * D_];
__device__ __nv_bfloat16 g_aoh[(size_t)B_ * N_ * D_];
__device__ __nv_bfloat16 g_aol[(size_t)B_ * N_ * D_];
__device__ __nv_bfloat16 g_wph[(size_t)D_ * D_];
__device__ __nv_bfloat16 g_wpl[(size_t)D_ * D_];
__device__ __nv_bfloat16 g_qh[(size_t)BH_ * N_ * HD_];
__device__ __nv_bfloat16 g_ql[(size_t)BH_ * N_ * HD_];
__device__ __nv_bfloat16 g_kh[(size_t)BH_ * N_ * HD_];
__device__ __nv_bfloat16 g_kl[(size_t)BH_ * N_ * HD_];
__device__ __nv_bfloat16 g_vh[(size_t)BH_ * HD_ * N_];  // [bh][d][n]
__device__ __nv_bfloat16 g_vl[(size_t)BH_ * HD_ * N_];
__device__ float g_cosT[(size_t)N_ * HD_];
__device__ float g_sinT[(size_t)N_ * HD_];

// ---------------- helpers ----------------
__device__ __forceinline__ void ldsm_x4(uint32_t* r, const void* p) {
    uint32_t a = (uint32_t)__cvta_generic_to_shared(p);
    asm volatile("ldmatrix.sync.aligned.m8n8.x4.shared.b16 {%0,%1,%2,%3}, [%4];"
                 : "=r"(r[0]), "=r"(r[1]), "=r"(r[2]), "=r"(r[3]) : "r"(a));
}
__device__ __forceinline__ void ldsm_x2(uint32_t* r, const void* p) {
    uint32_t a = (uint32_t)__cvta_generic_to_shared(p);
    asm volatile("ldmatrix.sync.aligned.m8n8.x2.shared.b16 {%0,%1}, [%2];"
                 : "=r"(r[0]), "=r"(r[1]) : "r"(a));
}
__device__ __forceinline__ void mma16816(float* c, const uint32_t* a, const uint32_t* b) {
    asm volatile(
        "mma.sync.aligned.m16n8k16.row.col.f32.bf16.bf16.f32 "
        "{%0,%1,%2,%3}, {%4,%5,%6,%7}, {%8,%9}, {%0,%1,%2,%3};"
        : "+f"(c[0]), "+f"(c[1]), "+f"(c[2]), "+f"(c[3])
        : "r"(a[0]), "r"(a[1]), "r"(a[2]), "r"(a[3]), "r"(b[0]), "r"(b[1]));
}
__device__ __forceinline__ void split2(float a, float b, uint32_t& h, uint32_t& l) {
    __nv_bfloat16 ha = __float2bfloat16(a), hb = __float2bfloat16(b);
    __nv_bfloat16 la = __float2bfloat16(a - __bfloat162float(ha));
    __nv_bfloat16 lb = __float2bfloat16(b - __bfloat162float(hb));
    h = (uint32_t)*(uint16_t*)&ha | ((uint32_t)*(uint16_t*)&hb << 16);
    l = (uint32_t)*(uint16_t*)&la | ((uint32_t)*(uint16_t*)&lb << 16);
}
__device__ __forceinline__ void cp16(void* s, const void* g) {
    uint32_t sa = (uint32_t)__cvta_generic_to_shared(s);
    asm volatile("cp.async.ca.shared.global [%0], [%1], 16;" :: "r"(sa), "l"(g));
}
#define CP_COMMIT() asm volatile("cp.async.commit_group;" ::: "memory")
#define CP_WAIT(n)  asm volatile("cp.async.wait_group %0;" :: "n"(n) : "memory")

// ---------------------------------------------------------------------------
// fused prologue: x split | Wqkv split | Wproj split | sincos table
// ---------------------------------------------------------------------------
#define NX4 ((B_ * N_ * D_) / 4)
#define NW4 ((QKVSTRIDE * D_) / 4)
#define NP4 ((D_ * D_) / 4)
#define NS_ (N_ * HD_)
#define PRO_TOTAL (NX4 + NW4 + NP4 + NS_)

__global__ void prologue_kernel(const float4* __restrict__ x,
                                const float4* __restrict__ wq,
                                const float4* __restrict__ wp,
                                const float* __restrict__ pe)
{
    int i = blockIdx.x * blockDim.x + threadIdx.x;
    if (i < NX4) {
        float4 v = x[i];
        uint2 ho, lo;
        split2(v.x, v.y, ho.x, lo.x);
        split2(v.z, v.w, ho.y, lo.y);
        ((uint2*)g_xh)[i] = ho; ((uint2*)g_xl)[i] = lo;
    } else if (i < NX4 + NW4) {
        int j = i - NX4;
        float4 v = wq[j];
        uint2 ho, lo;
        split2(v.x, v.y, ho.x, lo.x);
        split2(v.z, v.w, ho.y, lo.y);
        ((uint2*)g_wqh)[j] = ho; ((uint2*)g_wql)[j] = lo;
    } else if (i < NX4 + NW4 + NP4) {
        int j = i - NX4 - NW4;
        float4 v = wp[j];
        uint2 ho, lo;
        split2(v.x, v.y, ho.x, lo.x);
        split2(v.z, v.w, ho.y, lo.y);
        ((uint2*)g_wph)[j] = ho; ((uint2*)g_wpl)[j] = lo;
    } else if (i < PRO_TOTAL) {
        int j = i - NX4 - NW4 - NP4;
        float s, c;
        sincosf(pe[j], &s, &c);
        g_sinT[j] = s;
        g_cosT[j] = c;
    }
}

// ---------------------------------------------------------------------------
// HMMA GEMM — R10 proven mainloop, 128x128 CTA tile, fused QKV epilogue.
// ---------------------------------------------------------------------------
#define SSTR 40
#define GEMM_ASZ (128 * SSTR)
#define GEMM_STG (4 * GEMM_ASZ)
#define GEMM_SMEM (2 * GEMM_STG * 2)   // 81920 bytes
#define ESTR 132

__global__ __launch_bounds__(256) void gemm_qkv_kernel(
    const __nv_bfloat16* __restrict__ Ah, const __nv_bfloat16* __restrict__ Al,
    const __nv_bfloat16* __restrict__ Wh, const __nv_bfloat16* __restrict__ Wl,
    int M, int Nc, int K)
{
    extern __shared__ __nv_bfloat16 gsm[];

    const int tid  = threadIdx.x;
    const int lane = tid & 31;
    const int wid  = tid >> 5;
    const int wm   = wid & 1;
    const int wn   = wid >> 1;
    const int m0   = blockIdx.y * 128;
    const int n0   = blockIdx.x * 128;

    float acc[4][4][4];
#pragma unroll
    for (int mt = 0; mt < 4; mt++)
#pragma unroll
        for (int nt = 0; nt < 4; nt++)
#pragma unroll
            for (int e = 0; e < 4; e++) acc[mt][nt][e] = 0.f;

    const int nkt = K / 32;

    auto load_stage = [&](int st, int t) {
        __nv_bfloat16* base = gsm + st * GEMM_STG;
        const int kk = t * 32;
        for (int f = tid; f < 512; f += 256) {
            int row = f >> 2;
            int ch  = (f & 3) * 8;
            size_t ga = (size_t)(m0 + row) * K + kk + ch;
            size_t gw = (size_t)(n0 + row) * K + kk + ch;
            int so = row * SSTR + ch;
            cp16(base + so,                Ah + ga);
            cp16(base + GEMM_ASZ + so,     Al + ga);
            cp16(base + 2 * GEMM_ASZ + so, Wh + gw);
            cp16(base + 3 * GEMM_ASZ + so, Wl + gw);
        }
    };

    load_stage(0, 0);
    CP_COMMIT();

    for (int t = 0; t < nkt; t++) {
        const int cur = t & 1;
        if (t + 1 < nkt) {
            load_stage(cur ^ 1, t + 1);
            CP_COMMIT();
            CP_WAIT(1);
        } else {
            CP_WAIT(0);
        }
        __syncthreads();

        const __nv_bfloat16* sAh = gsm + cur * GEMM_STG;
        const __nv_bfloat16* sAl = sAh + GEMM_ASZ;
        const __nv_bfloat16* sWh = sAh + 2 * GEMM_ASZ;
        const __nv_bfloat16* sWl = sAh + 3 * GEMM_ASZ;

#pragma unroll
        for (int ks = 0; ks < 2; ks++) {
            uint32_t ah[4][4], al[4][4], bh[4][2], bl[4][2];
            const int acol = ks * 16 + (lane >> 4) * 8;
            const int bcol = ks * 16 + ((lane >> 3) & 1) * 8;
#pragma unroll
            for (int mt = 0; mt < 4; mt++) {
                int r = wm * 64 + mt * 16 + (lane & 15);
                ldsm_x4(ah[mt], &sAh[r * SSTR + acol]);
                ldsm_x4(al[mt], &sAl[r * SSTR + acol]);
            }
#pragma unroll
            for (int nt = 0; nt < 4; nt++) {
                int r = wn * 32 + nt * 8 + (lane & 7);
                ldsm_x2(bh[nt], &sWh[r * SSTR + bcol]);
                ldsm_x2(bl[nt], &sWl[r * SSTR + bcol]);
            }
#pragma unroll
            for (int mt = 0; mt < 4; mt++)
#pragma unroll
                for (int nt = 0; nt < 4; nt++)
                    mma16816(acc[mt][nt], ah[mt], bh[nt]);
#pragma unroll
            for (int mt = 0; mt < 4; mt++)
#pragma unroll
                for (int nt = 0; nt < 4; nt++)
                    mma16816(acc[mt][nt], ah[mt], bl[nt]);
#pragma unroll
            for (int mt = 0; mt < 4; mt++)
#pragma unroll
                for (int nt = 0; nt < 4; nt++)
                    mma16816(acc[mt][nt], al[mt], bh[nt]);
        }
        __syncthreads();
    }

    // fused QKV epilogue
    float* smf = (float*)gsm;
#pragma unroll
    for (int mt = 0; mt < 4; mt++) {
        int rl = wm * 64 + mt * 16 + (lane >> 2);
#pragma unroll
        for (int nt = 0; nt < 4; nt++) {
            int cl = wn * 32 + nt * 8 + (lane & 3) * 2;
            float2 v0 = {acc[mt][nt][0], acc[mt][nt][1]};
            float2 v1 = {acc[mt][nt][2], acc[mt][nt][3]};
            *(float2*)&smf[rl * ESTR + cl]       = v0;
            *(float2*)&smf[(rl + 8) * ESTR + cl] = v1;
        }
    }
    __syncthreads();

    const int b   = m0 >> 11;
    const int nt0 = m0 & (N_ - 1);

    if (n0 < 2 * D_) {
        const bool isq = (n0 < D_);
        const int cbase = isq ? n0 : (n0 - D_);
        __nv_bfloat16* dh = isq ? g_qh : g_kh;
        __nv_bfloat16* dl = isq ? g_ql : g_kl;
        const float qs = isq ? 0.125f : 1.0f;
        for (int f = tid; f < 8192; f += 256) {
            int r  = f >> 6;
            int c2 = (f & 63) * 2;
            int cg = cbase + c2;
            int h  = cg >> 6;
            int d  = cg & 63;
            int n  = nt0 + r;
            float2 x = *(const float2*)&smf[r * ESTR + c2];
            float2 p = *(const float2*)&smf[r * ESTR + (c2 ^ 32)];
            float2 cs = *(const float2*)&g_cosT[n * HD_ + d];
            float2 sn = *(const float2*)&g_sinT[n * HD_ + d];
            float sgn = (d < 32) ? -1.f : 1.f;
            float o0 = (x.x * cs.x + sgn * p.x * sn.x) * qs;
            float o1 = (x.y * cs.y + sgn * p.y * sn.y) * qs;
            uint32_t hh, ll;
            split2(o0, o1, hh, ll);
            size_t dst = ((size_t)(b * H_ + h) * N_ + n) * HD_ + d;
            *(uint32_t*)&dh[dst] = hh;
            *(uint32_t*)&dl[dst] = ll;
        }
    } else {
        const int cbase = n0 - 2 * D_;
        for (int f = tid; f < 8192; f += 256) {
            int c  = f >> 6;
            int np = (f & 63) * 2;
            int cg = cbase + c;
            int h  = cg >> 6;
            int d  = cg & 63;
            float v0 = smf[np * ESTR + c];
            float v1 = smf[(np + 1) * ESTR + c];
            uint32_t hh, ll;
            split2(v0, v1, hh, ll);
            size_t dst = ((size_t)(b * H_ + h) * HD_ + d) * N_ + nt0 + np;
            *(uint32_t*)&g_vh[dst] = hh;
            *(uint32_t*)&g_vl[dst] = ll;
        }
    }
}

// ---------------------------------------------------------------------------
// Out-proj GEMM — 64x128 CTA tile (384 CTAs -> better wave balance, lower
// regs, 2 CTAs/SM possible). 8 warps x 32x32 warp tiles; same mainloop style.
// ---------------------------------------------------------------------------
#define G64_AT (64 * SSTR)              // 2560 elems per A array per stage
#define G64_WT (128 * SSTR)             // 5120 elems per W array per stage
#define G64_STG (2 * G64_AT + 2 * G64_WT)  // 15360 elems
#define G64_SMEM (2 * G64_STG * 2)      // 61440 bytes

__global__ __launch_bounds__(256) void gemm_out_kernel(
    const __nv_bfloat16* __restrict__ Ah, const __nv_bfloat16* __restrict__ Al,
    const __nv_bfloat16* __restrict__ Wh, const __nv_bfloat16* __restrict__ Wl,
    const float* __restrict__ bias, float* __restrict__ C,
    int M, int Nc, int K)
{
    extern __shared__ __nv_bfloat16 gsm[];

    const int tid  = threadIdx.x;
    const int lane = tid & 31;
    const int wid  = tid >> 5;
    const int wm   = wid & 1;      // 2 m-tiles of 32 rows
    const int wn   = wid >> 1;     // 4 n-tiles of 32 cols
    const int m0   = blockIdx.y * 64;
    const int n0   = blockIdx.x * 128;

    float acc[2][4][4];
#pragma unroll
    for (int mt = 0; mt < 2; mt++)
#pragma unroll
        for (int nt = 0; nt < 4; nt++)
#pragma unroll
            for (int e = 0; e < 4; e++) acc[mt][nt][e] = 0.f;

    const int nkt = K / 32;

    auto load_stage = [&](int st, int t) {
        __nv_bfloat16* base = gsm + st * G64_STG;
        const int kk = t * 32;
        // A: 64 rows (256 chunks/array)
        {
            int row = tid >> 2;
            int ch  = (tid & 3) * 8;
            size_t ga = (size_t)(m0 + row) * K + kk + ch;
            int so = row * SSTR + ch;
            cp16(base + so,          Ah + ga);
            cp16(base + G64_AT + so, Al + ga);
        }
        // W: 128 rows (512 chunks/array)
        for (int f = tid; f < 512; f += 256) {
            int row = f >> 2;
            int ch  = (f & 3) * 8;
            size_t gw = (size_t)(n0 + row) * K + kk + ch;
            int so = row * SSTR + ch;
            cp16(base + 2 * G64_AT + so,           Wh + gw);
            cp16(base + 2 * G64_AT + G64_WT + so,  Wl + gw);
        }
    };

    load_stage(0, 0);
    CP_COMMIT();

    for (int t = 0; t < nkt; t++) {
        const int cur = t & 1;
        if (t + 1 < nkt) {
            load_stage(cur ^ 1, t + 1);
            CP_COMMIT();
            CP_WAIT(1);
        } else {
            CP_WAIT(0);
        }
        __syncthreads();

        const __nv_bfloat16* sAh = gsm + cur * G64_STG;
        const __nv_bfloat16* sAl = sAh + G64_AT;
        const __nv_bfloat16* sWh = sAh + 2 * G64_AT;
        const __nv_bfloat16* sWl = sWh + G64_WT;

#pragma unroll
        for (int ks = 0; ks < 2; ks++) {
            uint32_t ah[2][4], al[2][4], bh[4][2], bl[4][2];
            const int acol = ks * 16 + (lane >> 4) * 8;
            const int bcol = ks * 16 + ((lane >> 3) & 1) * 8;
#pragma unroll
            for (int mt = 0; mt < 2; mt++) {
                int r = wm * 32 + mt * 16 + (lane & 15);
                ldsm_x4(ah[mt], &sAh[r * SSTR + acol]);
                ldsm_x4(al[mt], &sAl[r * SSTR + acol]);
            }
#pragma unroll
            for (int nt = 0; nt < 4; nt++) {
                int r = wn * 32 + nt * 8 + (lane & 7);
                ldsm_x2(bh[nt], &sWh[r * SSTR + bcol]);
                ldsm_x2(bl[nt], &sWl[r * SSTR + bcol]);
            }
#pragma unroll
            for (int mt = 0; mt < 2; mt++)
#pragma unroll
                for (int nt = 0; nt < 4; nt++)
                    mma16816(acc[mt][nt], ah[mt], bh[nt]);
#pragma unroll
            for (int mt = 0; mt < 2; mt++)
#pragma unroll
                for (int nt = 0; nt < 4; nt++)
                    mma16816(acc[mt][nt], ah[mt], bl[nt]);
#pragma unroll
            for (int mt = 0; mt < 2; mt++)
#pragma unroll
                for (int nt = 0; nt < 4; nt++)
                    mma16816(acc[mt][nt], al[mt], bh[nt]);
        }
        __syncthreads();
    }

#pragma unroll
    for (int mt = 0; mt < 2; mt++) {
        int m = m0 + wm * 32 + mt * 16 + (lane >> 2);
#pragma unroll
        for (int nt = 0; nt < 4; nt++) {
            int n = n0 + wn * 32 + nt * 8 + (lane & 3) * 2;
            float2 bb = *(const float2*)&bias[n];
            float2 v0 = {acc[mt][nt][0] + bb.x, acc[mt][nt][1] + bb.y};
            float2 v1 = {acc[mt][nt][2] + bb.x, acc[mt][nt][3] + bb.y};
            *(float2*)&C[(size_t)m * Nc + n]       = v0;
            *(float2*)&C[(size_t)(m + 8) * Nc + n] = v1;
        }
    }
}

// ---------------------------------------------------------------------------
// Tensor-core flash attention — R13/R15 proven.
// ---------------------------------------------------------------------------
#define QKS 72
#define VTS 136
#define A_QT   (128 * QKS)
#define A_KT   (128 * QKS)
#define A_VT   (64 * VTS)
#define A_STG  (2 * A_KT + 2 * A_VT)
#define A_SMEM ((2 * A_QT + 2 * A_STG) * 2)

__global__ __launch_bounds__(256, 1) void attn_mma_kernel()
{
    extern __shared__ __nv_bfloat16 smb[];
    __nv_bfloat16* sQh = smb;
    __nv_bfloat16* sQl = smb + A_QT;
    __nv_bfloat16* stage0 = smb + 2 * A_QT;

    const int tid  = threadIdx.x;
    const int lane = tid & 31;
    const int wid  = tid >> 5;
    const int w16  = wid * 16;
    const int bh   = blockIdx.y;
    const int b    = bh / H_;
    const int h    = bh % H_;
    const int q0   = blockIdx.x * 128;

    const __nv_bfloat16* qhb = g_qh + (size_t)bh * N_ * HD_;
    const __nv_bfloat16* qlb = g_ql + (size_t)bh * N_ * HD_;
    const __nv_bfloat16* khb = g_kh + (size_t)bh * N_ * HD_;
    const __nv_bfloat16* klb = g_kl + (size_t)bh * N_ * HD_;
    const __nv_bfloat16* vhb = g_vh + (size_t)bh * HD_ * N_;
    const __nv_bfloat16* vlb = g_vl + (size_t)bh * HD_ * N_;

    for (int f = tid; f < 1024; f += 256) {
        int row = f >> 3;
        int ch  = (f & 7) * 8;
        *(uint4*)&sQh[row * QKS + ch] = *(const uint4*)(qhb + (size_t)(q0 + row) * HD_ + ch);
        *(uint4*)&sQl[row * QKS + ch] = *(const uint4*)(qlb + (size_t)(q0 + row) * HD_ + ch);
    }

    auto load_stage = [&](int st, int kt) {
        __nv_bfloat16* base = stage0 + st * A_STG;
        const int k0 = kt * 128;
        for (int f = tid; f < 1024; f += 256) {
            int row = f >> 3;
            int ch  = (f & 7) * 8;
            size_t g = (size_t)(k0 + row) * HD_ + ch;
            int so = row * QKS + ch;
            cp16(base + so,        khb + g);
            cp16(base + A_KT + so, klb + g);
        }
        __nv_bfloat16* vb = base + 2 * A_KT;
        for (int f = tid; f < 1024; f += 256) {
            int d  = f >> 4;
            int ch = (f & 15) * 8;
            size_t g = (size_t)d * N_ + k0 + ch;
            int so = d * VTS + ch;
            cp16(vb + so,        vhb + g);
            cp16(vb + A_VT + so, vlb + g);
        }
    };

    float oacc[8][4];
#pragma unroll
    for (int ob = 0; ob < 8; ob++)
#pragma unroll
        for (int e = 0; e < 4; e++) oacc[ob][e] = 0.f;
    float m0 = -1e30f, m1 = -1e30f, l0 = 0.f, l1 = 0.f;

    load_stage(0, 0);
    CP_COMMIT();

    for (int kt = 0; kt < N_ / 128; kt++) {
        const int cur = kt & 1;
        if (kt + 1 < N_ / 128) {
            load_stage(cur ^ 1, kt + 1);
            CP_COMMIT();
            CP_WAIT(1);
        } else {
            CP_WAIT(0);
        }
        __syncthreads();

        const __nv_bfloat16* sKh = stage0 + cur * A_STG;
        const __nv_bfloat16* sKl = sKh + A_KT;
        const __nv_bfloat16* sVh = sKh + 2 * A_KT;
        const __nv_bfloat16* sVl = sVh + A_VT;

        float sacc[16][4];
#pragma unroll
        for (int nb = 0; nb < 16; nb++)
#pragma unroll
            for (int e = 0; e < 4; e++) sacc[nb][e] = 0.f;

#pragma unroll
        for (int ks = 0; ks < 4; ks++) {
            uint32_t ah[4], al[4];
            const int acol = ks * 16 + (lane >> 4) * 8;
            ldsm_x4(ah, &sQh[(w16 + (lane & 15)) * QKS + acol]);
            ldsm_x4(al, &sQl[(w16 + (lane & 15)) * QKS + acol]);
            const int bcol = ks * 16 + ((lane >> 3) & 1) * 8;
#pragma unroll
            for (int g = 0; g < 4; g++) {
                uint32_t bhf[4][2], blf[4][2];
#pragma unroll
                for (int q = 0; q < 4; q++) {
                    int nb = g * 4 + q;
                    ldsm_x2(bhf[q], &sKh[(nb * 8 + (lane & 7)) * QKS + bcol]);
                    ldsm_x2(blf[q], &sKl[(nb * 8 + (lane & 7)) * QKS + bcol]);
                }
#pragma unroll
                for (int q = 0; q < 4; q++) mma16816(sacc[g * 4 + q], ah, bhf[q]);
#pragma unroll
                for (int q = 0; q < 4; q++) mma16816(sacc[g * 4 + q], ah, blf[q]);
#pragma unroll
                for (int q = 0; q < 4; q++) mma16816(sacc[g * 4 + q], al, bhf[q]);
            }
        }

        float mx0 = -1e30f, mx1 = -1e30f;
#pragma unroll
        for (int nb = 0; nb < 16; nb++) {
            mx0 = fmaxf(mx0, fmaxf(sacc[nb][0], sacc[nb][1]));
            mx1 = fmaxf(mx1, fmaxf(sacc[nb][2], sacc[nb][3]));
        }
        mx0 = fmaxf(mx0, __shfl_xor_sync(0xffffffffu, mx0, 1));
        mx0 = fmaxf(mx0, __shfl_xor_sync(0xffffffffu, mx0, 2));
        mx1 = fmaxf(mx1, __shfl_xor_sync(0xffffffffu, mx1, 1));
        mx1 = fmaxf(mx1, __shfl_xor_sync(0xffffffffu, mx1, 2));

        float mn0 = fmaxf(m0, mx0);
        float mn1 = fmaxf(m1, mx1);
        float cr0 = __expf(m0 - mn0);
        float cr1 = __expf(m1 - mn1);
        m0 = mn0; m1 = mn1;

        float rs0 = 0.f, rs1 = 0.f;
#pragma unroll
        for (int nb = 0; nb < 16; nb++) {
            sacc[nb][0] = __expf(sacc[nb][0] - mn0);
            sacc[nb][1] = __expf(sacc[nb][1] - mn0);
            sacc[nb][2] = __expf(sacc[nb][2] - mn1);
            sacc[nb][3] = __expf(sacc[nb][3] - mn1);
            rs0 += sacc[nb][0] + sacc[nb][1];
            rs1 += sacc[nb][2] + sacc[nb][3];
        }
        rs0 += __shfl_xor_sync(0xffffffffu, rs0, 1);
        rs0 += __shfl_xor_sync(0xffffffffu, rs0, 2);
        rs1 += __shfl_xor_sync(0xffffffffu, rs1, 1);
        rs1 += __shfl_xor_sync(0xffffffffu, rs1, 2);
        l0 = l0 * cr0 + rs0;
        l1 = l1 * cr1 + rs1;
#pragma unroll
        for (int ob = 0; ob < 8; ob++) {
            oacc[ob][0] *= cr0; oacc[ob][1] *= cr0;
            oacc[ob][2] *= cr1; oacc[ob][3] *= cr1;
        }

        uint32_t pah[8][4], pal[8][4];
#pragma unroll
        for (int kb = 0; kb < 8; kb++) {
            split2(sacc[2 * kb][0],     sacc[2 * kb][1],     pah[kb][0], pal[kb][0]);
            split2(sacc[2 * kb][2],     sacc[2 * kb][3],     pah[kb][1], pal[kb][1]);
            split2(sacc[2 * kb + 1][0], sacc[2 * kb + 1][1], pah[kb][2], pal[kb][2]);
            split2(sacc[2 * kb + 1][2], sacc[2 * kb + 1][3], pah[kb][3], pal[kb][3]);
        }

#pragma unroll
        for (int kb = 0; kb < 8; kb++) {
            const int bcol = kb * 16 + ((lane >> 3) & 1) * 8;
            uint32_t vhf[8][2], vlf[8][2];
#pragma unroll
            for (int ob = 0; ob < 8; ob++) {
                ldsm_x2(vhf[ob], &sVh[(ob * 8 + (lane & 7)) * VTS + bcol]);
                ldsm_x2(vlf[ob], &sVl[(ob * 8 + (lane & 7)) * VTS + bcol]);
            }
#pragma unroll
            for (int ob = 0; ob < 8; ob++) mma16816(oacc[ob], pah[kb], vhf[ob]);
#pragma unroll
            for (int ob = 0; ob < 8; ob++) mma16816(oacc[ob], pah[kb], vlf[ob]);
#pragma unroll
            for (int ob = 0; ob < 8; ob++) mma16816(oacc[ob], pal[kb], vhf[ob]);
        }
        __syncthreads();
    }

    float inv0 = 1.f / l0;
    float inv1 = 1.f / l1;
    const int r0 = q0 + w16 + (lane >> 2);
#pragma unroll
    for (int ob = 0; ob < 8; ob++) {
        int col = h * HD_ + ob * 8 + (lane & 3) * 2;
        size_t i0 = (size_t)(b * N_ + r0) * D_ + col;
        size_t i1 = (size_t)(b * N_ + r0 + 8) * D_ + col;
        uint32_t hh, ll;
        split2(oacc[ob][0] * inv0, oacc[ob][1] * inv0, hh, ll);
        *(uint32_t*)&g_aoh[i0] = hh;
        *(uint32_t*)&g_aol[i0] = ll;
        split2(oacc[ob][2] * inv1, oacc[ob][3] * inv1, hh, ll);
        *(uint32_t*)&g_aoh[i1] = hh;
        *(uint32_t*)&g_aol[i1] = ll;
    }
}

// ---------------------------------------------------------------------------
extern "C" void kernel_launch(void* const* d_in, const int* in_sizes, int n_in,
                              void* d_out, int out_size)
{
    const float* x     = (const float*)d_in[0];
    const float* pe    = (const float*)d_in[1];
    const float* Wqkv  = (const float*)d_in[2];
    const float* Wproj = (const float*)d_in[3];
    const float* bproj = (const float*)d_in[4];
    float* out = (float*)d_out;

    __nv_bfloat16 *xh, *xl, *wqh, *wql, *aoh, *aol, *wph, *wpl;
    cudaGetSymbolAddress((void**)&xh,  g_xh);
    cudaGetSymbolAddress((void**)&xl,  g_xl);
    cudaGetSymbolAddress((void**)&wqh, g_wqh);
    cudaGetSymbolAddress((void**)&wql, g_wql);
    cudaGetSymbolAddress((void**)&aoh, g_aoh);
    cudaGetSymbolAddress((void**)&aol, g_aol);
    cudaGetSymbolAddress((void**)&wph, g_wph);
    cudaGetSymbolAddress((void**)&wpl, g_wpl);

    const int M = B_ * N_;           // 4096

    // 0) fused prologue
    {
        int blocks = (PRO_TOTAL + 255) / 256;
        prologue_kernel<<<blocks, 256>>>((const float4*)x, (const float4*)Wqkv,
                                         (const float4*)Wproj, pe);
    }
    // 1) QKV projection with fused RoPE + split + V-transpose epilogue
    {
        cudaFuncSetAttribute(gemm_qkv_kernel,
                             cudaFuncAttributeMaxDynamicSharedMemorySize, GEMM_SMEM);
        dim3 grid(QKVSTRIDE / 128, M / 128);
        gemm_qkv_kernel<<<grid, 256, GEMM_SMEM>>>(xh, xl, wqh, wql, M, QKVSTRIDE, D_);
    }
    // 2) Attention
    {
        cudaFuncSetAttribute(attn_mma_kernel,
                             cudaFuncAttributeMaxDynamicSharedMemorySize, A_SMEM);
        dim3 grid(N_ / 128, BH_);
        attn_mma_kernel<<<grid, 256, A_SMEM>>>();
    }
    // 3) output projection — 64x128 tiles, 384 CTAs
    {
        cudaFuncSetAttribute(gemm_out_kernel,
                             cudaFuncAttributeMaxDynamicSharedMemorySize, G64_SMEM);
        dim3 grid(D_ / 128, M / 64);
        gemm_out_kernel<<<grid, 256, G64_SMEM>>>(aoh, aol, wph, wpl, bproj, out,
                                                 M, D_, D_);
    }
}

// round 17
// speedup vs baseline: 1.0819x; 1.0041x over previous
#include <cuda_runtime.h>
#include <cuda_bf16.h>
#include <cstdint>
#include <math.h>

#define B_ 2
#define N_ 2048
#define D_ 768
#define H_ 12
#define HD_ 64
#define QKVSTRIDE (3 * D_)   // 2304
#define BH_ (B_ * H_)        // 24
#define LOG2E 1.4426950408889634f

// ---------------- scratch (allocation-free) ----------------
__device__ __nv_bfloat16 g_xh[(size_t)B_ * N_ * D_];
__device__ __nv_bfloat16 g_xl[(size_t)B_ * N_ * D_];
__device__ __nv_bfloat16 g_wqh[(size_t)QKVSTRIDE * D_];
__device__ __nv_bfloat16 g_wql[(size_t)QKVSTRIDE * D_];
__device__ __nv_bfloat16 g_aoh[(size_t)B_ * N_ * D_];
__device__ __nv_bfloat16 g_aol[(size_t)B_ * N_ * D_];
__device__ __nv_bfloat16 g_wph[(size_t)D_ * D_];
__device__ __nv_bfloat16 g_wpl[(size_t)D_ * D_];
__device__ __nv_bfloat16 g_qh[(size_t)BH_ * N_ * HD_];   // pre-scaled by 0.125*log2e
__device__ __nv_bfloat16 g_ql[(size_t)BH_ * N_ * HD_];
__device__ __nv_bfloat16 g_kh[(size_t)BH_ * N_ * HD_];
__device__ __nv_bfloat16 g_kl[(size_t)BH_ * N_ * HD_];
__device__ __nv_bfloat16 g_vh[(size_t)BH_ * HD_ * N_];   // [bh][d][n]
__device__ __nv_bfloat16 g_vl[(size_t)BH_ * HD_ * N_];
__device__ float g_cosT[(size_t)N_ * HD_];
__device__ float g_sinT[(size_t)N_ * HD_];

// ---------------- helpers ----------------
__device__ __forceinline__ void ldsm_x4(uint32_t* r, const void* p) {
    uint32_t a = (uint32_t)__cvta_generic_to_shared(p);
    asm volatile("ldmatrix.sync.aligned.m8n8.x4.shared.b16 {%0,%1,%2,%3}, [%4];"
                 : "=r"(r[0]), "=r"(r[1]), "=r"(r[2]), "=r"(r[3]) : "r"(a));
}
__device__ __forceinline__ void ldsm_x2(uint32_t* r, const void* p) {
    uint32_t a = (uint32_t)__cvta_generic_to_shared(p);
    asm volatile("ldmatrix.sync.aligned.m8n8.x2.shared.b16 {%0,%1}, [%2];"
                 : "=r"(r[0]), "=r"(r[1]) : "r"(a));
}
__device__ __forceinline__ void mma16816(float* c, const uint32_t* a, const uint32_t* b) {
    asm volatile(
        "mma.sync.aligned.m16n8k16.row.col.f32.bf16.bf16.f32 "
        "{%0,%1,%2,%3}, {%4,%5,%6,%7}, {%8,%9}, {%0,%1,%2,%3};"
        : "+f"(c[0]), "+f"(c[1]), "+f"(c[2]), "+f"(c[3])
        : "r"(a[0]), "r"(a[1]), "r"(a[2]), "r"(a[3]), "r"(b[0]), "r"(b[1]));
}
__device__ __forceinline__ void split2(float a, float b, uint32_t& h, uint32_t& l) {
    __nv_bfloat16 ha = __float2bfloat16(a), hb = __float2bfloat16(b);
    __nv_bfloat16 la = __float2bfloat16(a - __bfloat162float(ha));
    __nv_bfloat16 lb = __float2bfloat16(b - __bfloat162float(hb));
    h = (uint32_t)*(uint16_t*)&ha | ((uint32_t)*(uint16_t*)&hb << 16);
    l = (uint32_t)*(uint16_t*)&la | ((uint32_t)*(uint16_t*)&lb << 16);
}
__device__ __forceinline__ void cp16(void* s, const void* g) {
    uint32_t sa = (uint32_t)__cvta_generic_to_shared(s);
    asm volatile("cp.async.ca.shared.global [%0], [%1], 16;" :: "r"(sa), "l"(g));
}
#define CP_COMMIT() asm volatile("cp.async.commit_group;" ::: "memory")
#define CP_WAIT(n)  asm volatile("cp.async.wait_group %0;" :: "n"(n) : "memory")

// ---------------------------------------------------------------------------
// fused prologue: x split | Wqkv split | Wproj split | sincos table
// ---------------------------------------------------------------------------
#define NX4 ((B_ * N_ * D_) / 4)
#define NW4 ((QKVSTRIDE * D_) / 4)
#define NP4 ((D_ * D_) / 4)
#define NS_ (N_ * HD_)
#define PRO_TOTAL (NX4 + NW4 + NP4 + NS_)

__global__ void prologue_kernel(const float4* __restrict__ x,
                                const float4* __restrict__ wq,
                                const float4* __restrict__ wp,
                                const float* __restrict__ pe)
{
    int i = blockIdx.x * blockDim.x + threadIdx.x;
    if (i < NX4) {
        float4 v = x[i];
        uint2 ho, lo;
        split2(v.x, v.y, ho.x, lo.x);
        split2(v.z, v.w, ho.y, lo.y);
        ((uint2*)g_xh)[i] = ho; ((uint2*)g_xl)[i] = lo;
    } else if (i < NX4 + NW4) {
        int j = i - NX4;
        float4 v = wq[j];
        uint2 ho, lo;
        split2(v.x, v.y, ho.x, lo.x);
        split2(v.z, v.w, ho.y, lo.y);
        ((uint2*)g_wqh)[j] = ho; ((uint2*)g_wql)[j] = lo;
    } else if (i < NX4 + NW4 + NP4) {
        int j = i - NX4 - NW4;
        float4 v = wp[j];
        uint2 ho, lo;
        split2(v.x, v.y, ho.x, lo.x);
        split2(v.z, v.w, ho.y, lo.y);
        ((uint2*)g_wph)[j] = ho; ((uint2*)g_wpl)[j] = lo;
    } else if (i < PRO_TOTAL) {
        int j = i - NX4 - NW4 - NP4;
        float s, c;
        sincosf(pe[j], &s, &c);
        g_sinT[j] = s;
        g_cosT[j] = c;
    }
}

// ---------------------------------------------------------------------------
// HMMA GEMM — 128x128 CTA tile, fused QKV epilogue (q scaled by 0.125*log2e).
// ---------------------------------------------------------------------------
#define SSTR 40
#define GEMM_ASZ (128 * SSTR)
#define GEMM_STG (4 * GEMM_ASZ)
#define GEMM_SMEM (2 * GEMM_STG * 2)   // 81920 bytes
#define ESTR 132

__global__ __launch_bounds__(256) void gemm_qkv_kernel(
    const __nv_bfloat16* __restrict__ Ah, const __nv_bfloat16* __restrict__ Al,
    const __nv_bfloat16* __restrict__ Wh, const __nv_bfloat16* __restrict__ Wl,
    int M, int Nc, int K)
{
    extern __shared__ __nv_bfloat16 gsm[];

    const int tid  = threadIdx.x;
    const int lane = tid & 31;
    const int wid  = tid >> 5;
    const int wm   = wid & 1;
    const int wn   = wid >> 1;
    const int m0   = blockIdx.y * 128;
    const int n0   = blockIdx.x * 128;

    float acc[4][4][4];
#pragma unroll
    for (int mt = 0; mt < 4; mt++)
#pragma unroll
        for (int nt = 0; nt < 4; nt++)
#pragma unroll
            for (int e = 0; e < 4; e++) acc[mt][nt][e] = 0.f;

    const int nkt = K / 32;

    auto load_stage = [&](int st, int t) {
        __nv_bfloat16* base = gsm + st * GEMM_STG;
        const int kk = t * 32;
        for (int f = tid; f < 512; f += 256) {
            int row = f >> 2;
            int ch  = (f & 3) * 8;
            size_t ga = (size_t)(m0 + row) * K + kk + ch;
            size_t gw = (size_t)(n0 + row) * K + kk + ch;
            int so = row * SSTR + ch;
            cp16(base + so,                Ah + ga);
            cp16(base + GEMM_ASZ + so,     Al + ga);
            cp16(base + 2 * GEMM_ASZ + so, Wh + gw);
            cp16(base + 3 * GEMM_ASZ + so, Wl + gw);
        }
    };

    load_stage(0, 0);
    CP_COMMIT();

    for (int t = 0; t < nkt; t++) {
        const int cur = t & 1;
        if (t + 1 < nkt) {
            load_stage(cur ^ 1, t + 1);
            CP_COMMIT();
            CP_WAIT(1);
        } else {
            CP_WAIT(0);
        }
        __syncthreads();

        const __nv_bfloat16* sAh = gsm + cur * GEMM_STG;
        const __nv_bfloat16* sAl = sAh + GEMM_ASZ;
        const __nv_bfloat16* sWh = sAh + 2 * GEMM_ASZ;
        const __nv_bfloat16* sWl = sAh + 3 * GEMM_ASZ;

#pragma unroll
        for (int ks = 0; ks < 2; ks++) {
            uint32_t ah[4][4], al[4][4], bh[4][2], bl[4][2];
            const int acol = ks * 16 + (lane >> 4) * 8;
            const int bcol = ks * 16 + ((lane >> 3) & 1) * 8;
#pragma unroll
            for (int mt = 0; mt < 4; mt++) {
                int r = wm * 64 + mt * 16 + (lane & 15);
                ldsm_x4(ah[mt], &sAh[r * SSTR + acol]);
                ldsm_x4(al[mt], &sAl[r * SSTR + acol]);
            }
#pragma unroll
            for (int nt = 0; nt < 4; nt++) {
                int r = wn * 32 + nt * 8 + (lane & 7);
                ldsm_x2(bh[nt], &sWh[r * SSTR + bcol]);
                ldsm_x2(bl[nt], &sWl[r * SSTR + bcol]);
            }
#pragma unroll
            for (int mt = 0; mt < 4; mt++)
#pragma unroll
                for (int nt = 0; nt < 4; nt++)
                    mma16816(acc[mt][nt], ah[mt], bh[nt]);
#pragma unroll
            for (int mt = 0; mt < 4; mt++)
#pragma unroll
                for (int nt = 0; nt < 4; nt++)
                    mma16816(acc[mt][nt], ah[mt], bl[nt]);
#pragma unroll
            for (int mt = 0; mt < 4; mt++)
#pragma unroll
                for (int nt = 0; nt < 4; nt++)
                    mma16816(acc[mt][nt], al[mt], bh[nt]);
        }
        __syncthreads();
    }

    // fused QKV epilogue
    float* smf = (float*)gsm;
#pragma unroll
    for (int mt = 0; mt < 4; mt++) {
        int rl = wm * 64 + mt * 16 + (lane >> 2);
#pragma unroll
        for (int nt = 0; nt < 4; nt++) {
            int cl = wn * 32 + nt * 8 + (lane & 3) * 2;
            float2 v0 = {acc[mt][nt][0], acc[mt][nt][1]};
            float2 v1 = {acc[mt][nt][2], acc[mt][nt][3]};
            *(float2*)&smf[rl * ESTR + cl]       = v0;
            *(float2*)&smf[(rl + 8) * ESTR + cl] = v1;
        }
    }
    __syncthreads();

    const int b   = m0 >> 11;
    const int nt0 = m0 & (N_ - 1);

    if (n0 < 2 * D_) {
        const bool isq = (n0 < D_);
        const int cbase = isq ? n0 : (n0 - D_);
        __nv_bfloat16* dh = isq ? g_qh : g_kh;
        __nv_bfloat16* dl = isq ? g_ql : g_kl;
        const float qs = isq ? (0.125f * LOG2E) : 1.0f;
        for (int f = tid; f < 8192; f += 256) {
            int r  = f >> 6;
            int c2 = (f & 63) * 2;
            int cg = cbase + c2;
            int h  = cg >> 6;
            int d  = cg & 63;
            int n  = nt0 + r;
            float2 x = *(const float2*)&smf[r * ESTR + c2];
            float2 p = *(const float2*)&smf[r * ESTR + (c2 ^ 32)];
            float2 cs = *(const float2*)&g_cosT[n * HD_ + d];
            float2 sn = *(const float2*)&g_sinT[n * HD_ + d];
            float sgn = (d < 32) ? -1.f : 1.f;
            float o0 = (x.x * cs.x + sgn * p.x * sn.x) * qs;
            float o1 = (x.y * cs.y + sgn * p.y * sn.y) * qs;
            uint32_t hh, ll;
            split2(o0, o1, hh, ll);
            size_t dst = ((size_t)(b * H_ + h) * N_ + n) * HD_ + d;
            *(uint32_t*)&dh[dst] = hh;
            *(uint32_t*)&dl[dst] = ll;
        }
    } else {
        const int cbase = n0 - 2 * D_;
        for (int f = tid; f < 8192; f += 256) {
            int c  = f >> 6;
            int np = (f & 63) * 2;
            int cg = cbase + c;
            int h  = cg >> 6;
            int d  = cg & 63;
            float v0 = smf[np * ESTR + c];
            float v1 = smf[(np + 1) * ESTR + c];
            uint32_t hh, ll;
            split2(v0, v1, hh, ll);
            size_t dst = ((size_t)(b * H_ + h) * HD_ + d) * N_ + nt0 + np;
            *(uint32_t*)&g_vh[dst] = hh;
            *(uint32_t*)&g_vl[dst] = ll;
        }
    }
}

// ---------------------------------------------------------------------------
// Out-proj GEMM — 64x128 CTA tile (R16 proven).
// ---------------------------------------------------------------------------
#define G64_AT (64 * SSTR)
#define G64_WT (128 * SSTR)
#define G64_STG (2 * G64_AT + 2 * G64_WT)
#define G64_SMEM (2 * G64_STG * 2)      // 61440 bytes

__global__ __launch_bounds__(256) void gemm_out_kernel(
    const __nv_bfloat16* __restrict__ Ah, const __nv_bfloat16* __restrict__ Al,
    const __nv_bfloat16* __restrict__ Wh, const __nv_bfloat16* __restrict__ Wl,
    const float* __restrict__ bias, float* __restrict__ C,
    int M, int Nc, int K)
{
    extern __shared__ __nv_bfloat16 gsm[];

    const int tid  = threadIdx.x;
    const int lane = tid & 31;
    const int wid  = tid >> 5;
    const int wm   = wid & 1;
    const int wn   = wid >> 1;
    const int m0   = blockIdx.y * 64;
    const int n0   = blockIdx.x * 128;

    float acc[2][4][4];
#pragma unroll
    for (int mt = 0; mt < 2; mt++)
#pragma unroll
        for (int nt = 0; nt < 4; nt++)
#pragma unroll
            for (int e = 0; e < 4; e++) acc[mt][nt][e] = 0.f;

    const int nkt = K / 32;

    auto load_stage = [&](int st, int t) {
        __nv_bfloat16* base = gsm + st * G64_STG;
        const int kk = t * 32;
        {
            int row = tid >> 2;
            int ch  = (tid & 3) * 8;
            size_t ga = (size_t)(m0 + row) * K + kk + ch;
            int so = row * SSTR + ch;
            cp16(base + so,          Ah + ga);
            cp16(base + G64_AT + so, Al + ga);
        }
        for (int f = tid; f < 512; f += 256) {
            int row = f >> 2;
            int ch  = (f & 3) * 8;
            size_t gw = (size_t)(n0 + row) * K + kk + ch;
            int so = row * SSTR + ch;
            cp16(base + 2 * G64_AT + so,          Wh + gw);
            cp16(base + 2 * G64_AT + G64_WT + so, Wl + gw);
        }
    };

    load_stage(0, 0);
    CP_COMMIT();

    for (int t = 0; t < nkt; t++) {
        const int cur = t & 1;
        if (t + 1 < nkt) {
            load_stage(cur ^ 1, t + 1);
            CP_COMMIT();
            CP_WAIT(1);
        } else {
            CP_WAIT(0);
        }
        __syncthreads();

        const __nv_bfloat16* sAh = gsm + cur * G64_STG;
        const __nv_bfloat16* sAl = sAh + G64_AT;
        const __nv_bfloat16* sWh = sAh + 2 * G64_AT;
        const __nv_bfloat16* sWl = sWh + G64_WT;

#pragma unroll
        for (int ks = 0; ks < 2; ks++) {
            uint32_t ah[2][4], al[2][4], bh[4][2], bl[4][2];
            const int acol = ks * 16 + (lane >> 4) * 8;
            const int bcol = ks * 16 + ((lane >> 3) & 1) * 8;
#pragma unroll
            for (int mt = 0; mt < 2; mt++) {
                int r = wm * 32 + mt * 16 + (lane & 15);
                ldsm_x4(ah[mt], &sAh[r * SSTR + acol]);
                ldsm_x4(al[mt], &sAl[r * SSTR + acol]);
            }
#pragma unroll
            for (int nt = 0; nt < 4; nt++) {
                int r = wn * 32 + nt * 8 + (lane & 7);
                ldsm_x2(bh[nt], &sWh[r * SSTR + bcol]);
                ldsm_x2(bl[nt], &sWl[r * SSTR + bcol]);
            }
#pragma unroll
            for (int mt = 0; mt < 2; mt++)
#pragma unroll
                for (int nt = 0; nt < 4; nt++)
                    mma16816(acc[mt][nt], ah[mt], bh[nt]);
#pragma unroll
            for (int mt = 0; mt < 2; mt++)
#pragma unroll
                for (int nt = 0; nt < 4; nt++)
                    mma16816(acc[mt][nt], ah[mt], bl[nt]);
#pragma unroll
            for (int mt = 0; mt < 2; mt++)
#pragma unroll
                for (int nt = 0; nt < 4; nt++)
                    mma16816(acc[mt][nt], al[mt], bh[nt]);
        }
        __syncthreads();
    }

#pragma unroll
    for (int mt = 0; mt < 2; mt++) {
        int m = m0 + wm * 32 + mt * 16 + (lane >> 2);
#pragma unroll
        for (int nt = 0; nt < 4; nt++) {
            int n = n0 + wn * 32 + nt * 8 + (lane & 3) * 2;
            float2 bb = *(const float2*)&bias[n];
            float2 v0 = {acc[mt][nt][0] + bb.x, acc[mt][nt][1] + bb.y};
            float2 v1 = {acc[mt][nt][2] + bb.x, acc[mt][nt][3] + bb.y};
            *(float2*)&C[(size_t)m * Nc + n]       = v0;
            *(float2*)&C[(size_t)(m + 8) * Nc + n] = v1;
        }
    }
}

// ---------------------------------------------------------------------------
// Tensor-core flash attention — R15 proven + hoisted Q fragments + exp2f.
// ---------------------------------------------------------------------------
#define QKS 72
#define VTS 136
#define A_QT   (128 * QKS)
#define A_KT   (128 * QKS)
#define A_VT   (64 * VTS)
#define A_STG  (2 * A_KT + 2 * A_VT)
#define A_SMEM ((2 * A_QT + 2 * A_STG) * 2)

__global__ __launch_bounds__(256, 1) void attn_mma_kernel()
{
    extern __shared__ __nv_bfloat16 smb[];
    __nv_bfloat16* sQh = smb;
    __nv_bfloat16* sQl = smb + A_QT;
    __nv_bfloat16* stage0 = smb + 2 * A_QT;

    const int tid  = threadIdx.x;
    const int lane = tid & 31;
    const int wid  = tid >> 5;
    const int w16  = wid * 16;
    const int bh   = blockIdx.y;
    const int b    = bh / H_;
    const int h    = bh % H_;
    const int q0   = blockIdx.x * 128;

    const __nv_bfloat16* qhb = g_qh + (size_t)bh * N_ * HD_;
    const __nv_bfloat16* qlb = g_ql + (size_t)bh * N_ * HD_;
    const __nv_bfloat16* khb = g_kh + (size_t)bh * N_ * HD_;
    const __nv_bfloat16* klb = g_kl + (size_t)bh * N_ * HD_;
    const __nv_bfloat16* vhb = g_vh + (size_t)bh * HD_ * N_;
    const __nv_bfloat16* vlb = g_vl + (size_t)bh * HD_ * N_;

    for (int f = tid; f < 1024; f += 256) {
        int row = f >> 3;
        int ch  = (f & 7) * 8;
        *(uint4*)&sQh[row * QKS + ch] = *(const uint4*)(qhb + (size_t)(q0 + row) * HD_ + ch);
        *(uint4*)&sQl[row * QKS + ch] = *(const uint4*)(qlb + (size_t)(q0 + row) * HD_ + ch);
    }

    auto load_stage = [&](int st, int kt) {
        __nv_bfloat16* base = stage0 + st * A_STG;
        const int k0 = kt * 128;
        for (int f = tid; f < 1024; f += 256) {
            int row = f >> 3;
            int ch  = (f & 7) * 8;
            size_t g = (size_t)(k0 + row) * HD_ + ch;
            int so = row * QKS + ch;
            cp16(base + so,        khb + g);
            cp16(base + A_KT + so, klb + g);
        }
        __nv_bfloat16* vb = base + 2 * A_KT;
        for (int f = tid; f < 1024; f += 256) {
            int d  = f >> 4;
            int ch = (f & 15) * 8;
            size_t g = (size_t)d * N_ + k0 + ch;
            int so = d * VTS + ch;
            cp16(vb + so,        vhb + g);
            cp16(vb + A_VT + so, vlb + g);
        }
    };

    float oacc[8][4];
#pragma unroll
    for (int ob = 0; ob < 8; ob++)
#pragma unroll
        for (int e = 0; e < 4; e++) oacc[ob][e] = 0.f;
    float m0 = -1e30f, m1 = -1e30f, l0 = 0.f, l1 = 0.f;

    load_stage(0, 0);
    CP_COMMIT();

    // ---- hoist Q fragments (loop-invariant) into registers ----
    __syncthreads();   // Q smem stores visible to all warps
    uint32_t qah[4][4], qal[4][4];
#pragma unroll
    for (int ks = 0; ks < 4; ks++) {
        const int acol = ks * 16 + (lane >> 4) * 8;
        ldsm_x4(qah[ks], &sQh[(w16 + (lane & 15)) * QKS + acol]);
        ldsm_x4(qal[ks], &sQl[(w16 + (lane & 15)) * QKS + acol]);
    }

    for (int kt = 0; kt < N_ / 128; kt++) {
        const int cur = kt & 1;
        if (kt + 1 < N_ / 128) {
            load_stage(cur ^ 1, kt + 1);
            CP_COMMIT();
            CP_WAIT(1);
        } else {
            CP_WAIT(0);
        }
        __syncthreads();

        const __nv_bfloat16* sKh = stage0 + cur * A_STG;
        const __nv_bfloat16* sKl = sKh + A_KT;
        const __nv_bfloat16* sVh = sKh + 2 * A_KT;
        const __nv_bfloat16* sVl = sVh + A_VT;

        // ---- S = Q @ K^T : groups of 4 accumulators, term-outer ----
        float sacc[16][4];
#pragma unroll
        for (int nb = 0; nb < 16; nb++)
#pragma unroll
            for (int e = 0; e < 4; e++) sacc[nb][e] = 0.f;

#pragma unroll
        for (int ks = 0; ks < 4; ks++) {
            const int bcol = ks * 16 + ((lane >> 3) & 1) * 8;
#pragma unroll
            for (int g = 0; g < 4; g++) {
                uint32_t bhf[4][2], blf[4][2];
#pragma unroll
                for (int q = 0; q < 4; q++) {
                    int nb = g * 4 + q;
                    ldsm_x2(bhf[q], &sKh[(nb * 8 + (lane & 7)) * QKS + bcol]);
                    ldsm_x2(blf[q], &sKl[(nb * 8 + (lane & 7)) * QKS + bcol]);
                }
#pragma unroll
                for (int q = 0; q < 4; q++) mma16816(sacc[g * 4 + q], qah[ks], bhf[q]);
#pragma unroll
                for (int q = 0; q < 4; q++) mma16816(sacc[g * 4 + q], qah[ks], blf[q]);
#pragma unroll
                for (int q = 0; q < 4; q++) mma16816(sacc[g * 4 + q], qal[ks], bhf[q]);
            }
        }

        // ---- online softmax (base-2 domain; Q pre-scaled by log2e) ----
        float mx0 = -1e30f, mx1 = -1e30f;
#pragma unroll
        for (int nb = 0; nb < 16; nb++) {
            mx0 = fmaxf(mx0, fmaxf(sacc[nb][0], sacc[nb][1]));
            mx1 = fmaxf(mx1, fmaxf(sacc[nb][2], sacc[nb][3]));
        }
        mx0 = fmaxf(mx0, __shfl_xor_sync(0xffffffffu, mx0, 1));
        mx0 = fmaxf(mx0, __shfl_xor_sync(0xffffffffu, mx0, 2));
        mx1 = fmaxf(mx1, __shfl_xor_sync(0xffffffffu, mx1, 1));
        mx1 = fmaxf(mx1, __shfl_xor_sync(0xffffffffu, mx1, 2));

        float mn0 = fmaxf(m0, mx0);
        float mn1 = fmaxf(m1, mx1);
        float cr0 = exp2f(m0 - mn0);
        float cr1 = exp2f(m1 - mn1);
        m0 = mn0; m1 = mn1;

        float rs0 = 0.f, rs1 = 0.f;
#pragma unroll
        for (int nb = 0; nb < 16; nb++) {
            sacc[nb][0] = exp2f(sacc[nb][0] - mn0);
            sacc[nb][1] = exp2f(sacc[nb][1] - mn0);
            sacc[nb][2] = exp2f(sacc[nb][2] - mn1);
            sacc[nb][3] = exp2f(sacc[nb][3] - mn1);
            rs0 += sacc[nb][0] + sacc[nb][1];
            rs1 += sacc[nb][2] + sacc[nb][3];
        }
        rs0 += __shfl_xor_sync(0xffffffffu, rs0, 1);
        rs0 += __shfl_xor_sync(0xffffffffu, rs0, 2);
        rs1 += __shfl_xor_sync(0xffffffffu, rs1, 1);
        rs1 += __shfl_xor_sync(0xffffffffu, rs1, 2);
        l0 = l0 * cr0 + rs0;
        l1 = l1 * cr1 + rs1;
#pragma unroll
        for (int ob = 0; ob < 8; ob++) {
            oacc[ob][0] *= cr0; oacc[ob][1] *= cr0;
            oacc[ob][2] *= cr1; oacc[ob][3] *= cr1;
        }

        // ---- pack P into bf16 hi/lo A fragments ----
        uint32_t pah[8][4], pal[8][4];
#pragma unroll
        for (int kb = 0; kb < 8; kb++) {
            split2(sacc[2 * kb][0],     sacc[2 * kb][1],     pah[kb][0], pal[kb][0]);
            split2(sacc[2 * kb][2],     sacc[2 * kb][3],     pah[kb][1], pal[kb][1]);
            split2(sacc[2 * kb + 1][0], sacc[2 * kb + 1][1], pah[kb][2], pal[kb][2]);
            split2(sacc[2 * kb + 1][2], sacc[2 * kb + 1][3], pah[kb][3], pal[kb][3]);
        }

        // ---- O += P @ V : kb-outer, term-outer over 8 oacc ----
#pragma unroll
        for (int kb = 0; kb < 8; kb++) {
            const int bcol = kb * 16 + ((lane >> 3) & 1) * 8;
            uint32_t vhf[8][2], vlf[8][2];
#pragma unroll
            for (int ob = 0; ob < 8; ob++) {
                ldsm_x2(vhf[ob], &sVh[(ob * 8 + (lane & 7)) * VTS + bcol]);
                ldsm_x2(vlf[ob], &sVl[(ob * 8 + (lane & 7)) * VTS + bcol]);
            }
#pragma unroll
            for (int ob = 0; ob < 8; ob++) mma16816(oacc[ob], pah[kb], vhf[ob]);
#pragma unroll
            for (int ob = 0; ob < 8; ob++) mma16816(oacc[ob], pah[kb], vlf[ob]);
#pragma unroll
            for (int ob = 0; ob < 8; ob++) mma16816(oacc[ob], pal[kb], vhf[ob]);
        }
        __syncthreads();
    }

    // ---- epilogue ----
    float inv0 = 1.f / l0;
    float inv1 = 1.f / l1;
    const int r0 = q0 + w16 + (lane >> 2);
#pragma unroll
    for (int ob = 0; ob < 8; ob++) {
        int col = h * HD_ + ob * 8 + (lane & 3) * 2;
        size_t i0 = (size_t)(b * N_ + r0) * D_ + col;
        size_t i1 = (size_t)(b * N_ + r0 + 8) * D_ + col;
        uint32_t hh, ll;
        split2(oacc[ob][0] * inv0, oacc[ob][1] * inv0, hh, ll);
        *(uint32_t*)&g_aoh[i0] = hh;
        *(uint32_t*)&g_aol[i0] = ll;
        split2(oacc[ob][2] * inv1, oacc[ob][3] * inv1, hh, ll);
        *(uint32_t*)&g_aoh[i1] = hh;
        *(uint32_t*)&g_aol[i1] = ll;
    }
}

// ---------------------------------------------------------------------------
extern "C" void kernel_launch(void* const* d_in, const int* in_sizes, int n_in,
                              void* d_out, int out_size)
{
    const float* x     = (const float*)d_in[0];
    const float* pe    = (const float*)d_in[1];
    const float* Wqkv  = (const float*)d_in[2];
    const float* Wproj = (const float*)d_in[3];
    const float* bproj = (const float*)d_in[4];
    float* out = (float*)d_out;

    __nv_bfloat16 *xh, *xl, *wqh, *wql, *aoh, *aol, *wph, *wpl;
    cudaGetSymbolAddress((void**)&xh,  g_xh);
    cudaGetSymbolAddress((void**)&xl,  g_xl);
    cudaGetSymbolAddress((void**)&wqh, g_wqh);
    cudaGetSymbolAddress((void**)&wql, g_wql);
    cudaGetSymbolAddress((void**)&aoh, g_aoh);
    cudaGetSymbolAddress((void**)&aol, g_aol);
    cudaGetSymbolAddress((void**)&wph, g_wph);
    cudaGetSymbolAddress((void**)&wpl, g_wpl);

    const int M = B_ * N_;           // 4096

    // 0) fused prologue
    {
        int blocks = (PRO_TOTAL + 255) / 256;
        prologue_kernel<<<blocks, 256>>>((const float4*)x, (const float4*)Wqkv,
                                         (const float4*)Wproj, pe);
    }
    // 1) QKV projection with fused RoPE + split + V-transpose epilogue
    {
        cudaFuncSetAttribute(gemm_qkv_kernel,
                             cudaFuncAttributeMaxDynamicSharedMemorySize, GEMM_SMEM);
        dim3 grid(QKVSTRIDE / 128, M / 128);
        gemm_qkv_kernel<<<grid, 256, GEMM_SMEM>>>(xh, xl, wqh, wql, M, QKVSTRIDE, D_);
    }
    // 2) Attention
    {
        cudaFuncSetAttribute(attn_mma_kernel,
                             cudaFuncAttributeMaxDynamicSharedMemorySize, A_SMEM);
        dim3 grid(N_ / 128, BH_);
        attn_mma_kernel<<<grid, 256, A_SMEM>>>();
    }
    // 3) output projection — 64x128 tiles
    {
        cudaFuncSetAttribute(gemm_out_kernel,
                             cudaFuncAttributeMaxDynamicSharedMemorySize, G64_SMEM);
        dim3 grid(D_ / 128, M / 64);
        gemm_out_kernel<<<grid, 256, G64_SMEM>>>(aoh, aol, wph, wpl, bproj, out,
                                                 M, D_, D_);
    }
}